// round 1
// baseline (speedup 1.0000x reference)
#include <cuda_runtime.h>
#include <math.h>
#include <stdint.h>

#define NB 1024
#define NN 128

// Scratch: hidden activations [B, N, 256], adjacency bitmasks, D^-1/2
__device__ float    g_H[(size_t)NB * NN * 256];
__device__ unsigned g_mask[NB * NN * 4];
__device__ float    g_dinv[NB * NN];

// ---------------------------------------------------------------------------
// Prep: binarize adjacency, add self loops, build 128-bit row masks + rsqrt(deg)
// One CTA per batch, warp per row (16 rows/warp).
// ---------------------------------------------------------------------------
__global__ __launch_bounds__(256) void prep_kernel(const float* __restrict__ adj) {
    int b    = blockIdx.x;
    int warp = threadIdx.x >> 5;
    int lane = threadIdx.x & 31;
    for (int r = warp; r < NN; r += 8) {
        const float* a = adj + ((size_t)b * NN + r) * NN;
        unsigned m[4];
        int deg = 0;
#pragma unroll
        for (int s = 0; s < 4; ++s) {
            float v = a[lane + 32 * s];
            unsigned w = __ballot_sync(0xffffffffu, v != 0.0f);
            if (s == (r >> 5)) w |= 1u << (r & 31);  // self loop
            m[s] = w;
            deg += __popc(w);
        }
        if (lane == 0) {
            g_dinv[b * NN + r] = rsqrtf((float)deg);
#pragma unroll
            for (int s = 0; s < 4; ++s) g_mask[(b * NN + r) * 4 + s] = m[s];
        }
    }
}

// ---------------------------------------------------------------------------
// One GCN layer: Hout = [elu]( A_norm @ (Hin @ W) + bias )
// One CTA per batch. Hin tile staged in SMEM. Dense GEMM (8x8 register tiles)
// computes T = (Hin @ W[:,chunk]) with rows pre-scaled by dinv_j; aggregation
// is a bitmask-driven sparse row-sum scaled by dinv_i.
// In-place safe: Hin fully loaded to SMEM before any global write.
// ---------------------------------------------------------------------------
template <int FIN, int FOUT, bool ELU>
__global__ __launch_bounds__(256, 1) void gcn_layer(
    const float* __restrict__ Hin, const float* __restrict__ W,
    const float* __restrict__ bias, float* __restrict__ Hout)
{
    constexpr int SHS = FIN + 4;   // padded strides (bank-conflict mitigation)
    constexpr int STS = 128 + 4;
    extern __shared__ float smem[];
    float*    sH    = smem;                       // [128][SHS]
    float*    sT    = sH + NN * SHS;              // [128][STS]
    float*    sW    = sT + NN * STS;              // [16][128]
    unsigned* sMask = (unsigned*)(sW + 16 * 128); // [128][4]
    float*    sDinv = (float*)(sMask + NN * 4);   // [128]

    const int b    = blockIdx.x;
    const int tid  = threadIdx.x;
    const int cx   = tid & 15;   // output-col tile
    const int cy   = tid >> 4;   // output-row tile
    const int warp = tid >> 5;
    const int lane = tid & 31;

    const float* hin = Hin + (size_t)b * NN * FIN;

    // Stage Hin (vectorized, coalesced)
    for (int i = tid; i < NN * FIN / 4; i += 256) {
        int r = i / (FIN / 4);
        int c = (i % (FIN / 4)) * 4;
        *(float4*)(sH + r * SHS + c) = *(const float4*)(hin + r * FIN + c);
    }
    for (int i = tid; i < NN * 4; i += 256) sMask[i] = g_mask[(size_t)b * NN * 4 + i];
    if (tid < NN) sDinv[tid] = g_dinv[b * NN + tid];
    __syncthreads();

    for (int ch = 0; ch < FOUT / 128; ++ch) {
        // ---- Dense GEMM: T = sH @ W[:, ch*128 : ch*128+128] ----
        float acc[8][8];
#pragma unroll
        for (int u = 0; u < 8; ++u)
#pragma unroll
            for (int v = 0; v < 8; ++v) acc[u][v] = 0.f;

        for (int k0 = 0; k0 < FIN; k0 += 16) {
            // Stage W k-tile [16][128]
#pragma unroll
            for (int i = 0; i < 2; ++i) {
                int idx = tid * 2 + i;           // 0..511
                int kk  = idx >> 5;              // row 0..15
                int c4  = (idx & 31) * 4;        // col (float4)
                *(float4*)(sW + kk * 128 + c4) =
                    *(const float4*)(W + (size_t)(k0 + kk) * FOUT + ch * 128 + c4);
            }
            __syncthreads();
#pragma unroll
            for (int kk = 0; kk < 16; ++kk) {
                float a[8];
#pragma unroll
                for (int u = 0; u < 8; ++u) a[u] = sH[(cy * 8 + u) * SHS + k0 + kk];
                float4 q0 = *(float4*)(sW + kk * 128 + cx * 8);
                float4 q1 = *(float4*)(sW + kk * 128 + cx * 8 + 4);
                float bb[8] = {q0.x, q0.y, q0.z, q0.w, q1.x, q1.y, q1.z, q1.w};
#pragma unroll
                for (int u = 0; u < 8; ++u)
#pragma unroll
                    for (int v = 0; v < 8; ++v) acc[u][v] = fmaf(a[u], bb[v], acc[u][v]);
            }
            __syncthreads();
        }
        // Pre-scale rows by dinv_j, store T to SMEM (vectorized)
#pragma unroll
        for (int u = 0; u < 8; ++u) {
            float di = sDinv[cy * 8 + u];
            float4 s0 = make_float4(acc[u][0] * di, acc[u][1] * di, acc[u][2] * di, acc[u][3] * di);
            float4 s1 = make_float4(acc[u][4] * di, acc[u][5] * di, acc[u][6] * di, acc[u][7] * di);
            *(float4*)(sT + (cy * 8 + u) * STS + cx * 8)     = s0;
            *(float4*)(sT + (cy * 8 + u) * STS + cx * 8 + 4) = s1;
        }
        __syncthreads();

        // ---- Sparse aggregation: out[i,f] = dinv_i * sum_{j in mask(i)} T[j,f] + b[f]
        float bq[4];
#pragma unroll
        for (int q = 0; q < 4; ++q) bq[q] = bias[ch * 128 + lane + 32 * q];

        for (int r = warp; r < NN; r += 8) {
            float s0 = 0.f, s1 = 0.f, s2 = 0.f, s3 = 0.f;
#pragma unroll
            for (int w = 0; w < 4; ++w) {
                unsigned bits = sMask[r * 4 + w];
                while (bits) {   // uniform across warp -> no divergence
                    int j = (w << 5) + (__ffs(bits) - 1);
                    bits &= bits - 1;
                    const float* tr = sT + j * STS + lane;
                    s0 += tr[0];
                    s1 += tr[32];
                    s2 += tr[64];
                    s3 += tr[96];
                }
            }
            float di = sDinv[r];
            float o[4] = {fmaf(di, s0, bq[0]), fmaf(di, s1, bq[1]),
                          fmaf(di, s2, bq[2]), fmaf(di, s3, bq[3])};
            if (ELU) {
#pragma unroll
                for (int q = 0; q < 4; ++q) o[q] = o[q] > 0.f ? o[q] : expm1f(o[q]);
            }
            float* orow = Hout + ((size_t)b * NN + r) * FOUT + ch * 128 + lane;
            orow[0]  = o[0];
            orow[32] = o[1];
            orow[64] = o[2];
            orow[96] = o[3];
        }
        __syncthreads();
    }
}

// ---------------------------------------------------------------------------
extern "C" void kernel_launch(void* const* d_in, const int* in_sizes, int n_in,
                              void* d_out, int out_size) {
    const float* x   = (const float*)d_in[0];
    const float* adj = (const float*)d_in[1];
    const float* W1  = (const float*)d_in[2];
    const float* b1  = (const float*)d_in[3];
    const float* W2  = (const float*)d_in[4];
    const float* b2  = (const float*)d_in[5];
    const float* W3  = (const float*)d_in[6];
    const float* b3  = (const float*)d_in[7];
    float* out = (float*)d_out;

    void* hp = nullptr;
    cudaGetSymbolAddress(&hp, g_H);
    float* H = (float*)hp;

    const int SM1 = (NN * (128 + 4) + NN * (128 + 4) + 16 * 128) * 4 + NN * 4 * 4 + NN * 4; // 145920
    const int SM2 = (NN * (256 + 4) + NN * (128 + 4) + 16 * 128) * 4 + NN * 4 * 4 + NN * 4; // 211456

    cudaFuncSetAttribute(gcn_layer<128, 256, true>,  cudaFuncAttributeMaxDynamicSharedMemorySize, SM1);
    cudaFuncSetAttribute(gcn_layer<256, 256, true>,  cudaFuncAttributeMaxDynamicSharedMemorySize, SM2);
    cudaFuncSetAttribute(gcn_layer<256, 128, false>, cudaFuncAttributeMaxDynamicSharedMemorySize, SM2);

    prep_kernel<<<NB, 256>>>(adj);
    gcn_layer<128, 256, true ><<<NB, 256, SM1>>>(x, W1, b1, H);
    gcn_layer<256, 256, true ><<<NB, 256, SM2>>>(H, W2, b2, H);
    gcn_layer<256, 128, false><<<NB, 256, SM2>>>(H, W3, b3, out);
}

// round 2
// speedup vs baseline: 1.0033x; 1.0033x over previous
#include <cuda_runtime.h>
#include <math.h>
#include <stdint.h>

#define NB 1024
#define NN 128

// Scratch: hidden activations [B, N, 256], adjacency bitmasks, D^-1/2
__device__ float    g_H[(size_t)NB * NN * 256];
__device__ unsigned g_mask[NB * NN * 4];
__device__ float    g_dinv[NB * NN];

// ---------------------------------------------------------------------------
// Prep: binarize adjacency, add self loops, build 128-bit row masks + rsqrt(deg)
// One CTA per batch, warp per row (16 rows/warp).
// ---------------------------------------------------------------------------
__global__ __launch_bounds__(256) void prep_kernel(const float* __restrict__ adj) {
    int b    = blockIdx.x;
    int warp = threadIdx.x >> 5;
    int lane = threadIdx.x & 31;
    for (int r = warp; r < NN; r += 8) {
        const float* a = adj + ((size_t)b * NN + r) * NN;
        unsigned m[4];
        int deg = 0;
#pragma unroll
        for (int s = 0; s < 4; ++s) {
            float v = a[lane + 32 * s];
            unsigned w = __ballot_sync(0xffffffffu, v != 0.0f);
            if (s == (r >> 5)) w |= 1u << (r & 31);  // self loop
            m[s] = w;
            deg += __popc(w);
        }
        if (lane == 0) {
            g_dinv[b * NN + r] = rsqrtf((float)deg);
#pragma unroll
            for (int s = 0; s < 4; ++s) g_mask[(b * NN + r) * 4 + s] = m[s];
        }
    }
}

// ---------------------------------------------------------------------------
// One GCN layer: Hout = [elu]( A_norm @ (Hin @ W) + bias )
// One CTA per batch. Hin tile staged in SMEM. Dense GEMM (8x8 register tiles)
// computes T = (Hin @ W[:,chunk]) with rows pre-scaled by dinv_j; aggregation
// is a bitmask-driven sparse row-sum scaled by dinv_i.
// In-place safe: Hin fully loaded to SMEM before any global write.
// ---------------------------------------------------------------------------
template <int FIN, int FOUT, bool ELU>
__global__ __launch_bounds__(256, 1) void gcn_layer(
    const float* __restrict__ Hin, const float* __restrict__ W,
    const float* __restrict__ bias, float* __restrict__ Hout)
{
    constexpr int SHS = FIN + 4;   // padded strides (bank-conflict mitigation)
    constexpr int STS = 128 + 4;
    extern __shared__ float smem[];
    float*    sH    = smem;                       // [128][SHS]
    float*    sT    = sH + NN * SHS;              // [128][STS]
    float*    sW    = sT + NN * STS;              // [16][128]
    unsigned* sMask = (unsigned*)(sW + 16 * 128); // [128][4]
    float*    sDinv = (float*)(sMask + NN * 4);   // [128]

    const int b    = blockIdx.x;
    const int tid  = threadIdx.x;
    const int cx   = tid & 15;   // output-col tile
    const int cy   = tid >> 4;   // output-row tile
    const int warp = tid >> 5;
    const int lane = tid & 31;

    const float* hin = Hin + (size_t)b * NN * FIN;

    // Stage Hin (vectorized, coalesced)
    for (int i = tid; i < NN * FIN / 4; i += 256) {
        int r = i / (FIN / 4);
        int c = (i % (FIN / 4)) * 4;
        *(float4*)(sH + r * SHS + c) = *(const float4*)(hin + r * FIN + c);
    }
    for (int i = tid; i < NN * 4; i += 256) sMask[i] = g_mask[(size_t)b * NN * 4 + i];
    if (tid < NN) sDinv[tid] = g_dinv[b * NN + tid];
    __syncthreads();

    for (int ch = 0; ch < FOUT / 128; ++ch) {
        // ---- Dense GEMM: T = sH @ W[:, ch*128 : ch*128+128] ----
        float acc[8][8];
#pragma unroll
        for (int u = 0; u < 8; ++u)
#pragma unroll
            for (int v = 0; v < 8; ++v) acc[u][v] = 0.f;

        for (int k0 = 0; k0 < FIN; k0 += 16) {
            // Stage W k-tile [16][128]
#pragma unroll
            for (int i = 0; i < 2; ++i) {
                int idx = tid * 2 + i;           // 0..511
                int kk  = idx >> 5;              // row 0..15
                int c4  = (idx & 31) * 4;        // col (float4)
                *(float4*)(sW + kk * 128 + c4) =
                    *(const float4*)(W + (size_t)(k0 + kk) * FOUT + ch * 128 + c4);
            }
            __syncthreads();
#pragma unroll
            for (int kk = 0; kk < 16; ++kk) {
                float a[8];
#pragma unroll
                for (int u = 0; u < 8; ++u) a[u] = sH[(cy * 8 + u) * SHS + k0 + kk];
                float4 q0 = *(float4*)(sW + kk * 128 + cx * 8);
                float4 q1 = *(float4*)(sW + kk * 128 + cx * 8 + 4);
                float bb[8] = {q0.x, q0.y, q0.z, q0.w, q1.x, q1.y, q1.z, q1.w};
#pragma unroll
                for (int u = 0; u < 8; ++u)
#pragma unroll
                    for (int v = 0; v < 8; ++v) acc[u][v] = fmaf(a[u], bb[v], acc[u][v]);
            }
            __syncthreads();
        }
        // Pre-scale rows by dinv_j, store T to SMEM (vectorized)
#pragma unroll
        for (int u = 0; u < 8; ++u) {
            float di = sDinv[cy * 8 + u];
            float4 s0 = make_float4(acc[u][0] * di, acc[u][1] * di, acc[u][2] * di, acc[u][3] * di);
            float4 s1 = make_float4(acc[u][4] * di, acc[u][5] * di, acc[u][6] * di, acc[u][7] * di);
            *(float4*)(sT + (cy * 8 + u) * STS + cx * 8)     = s0;
            *(float4*)(sT + (cy * 8 + u) * STS + cx * 8 + 4) = s1;
        }
        __syncthreads();

        // ---- Sparse aggregation: out[i,f] = dinv_i * sum_{j in mask(i)} T[j,f] + b[f]
        float bq[4];
#pragma unroll
        for (int q = 0; q < 4; ++q) bq[q] = bias[ch * 128 + lane + 32 * q];

        for (int r = warp; r < NN; r += 8) {
            float s0 = 0.f, s1 = 0.f, s2 = 0.f, s3 = 0.f;
#pragma unroll
            for (int w = 0; w < 4; ++w) {
                unsigned bits = sMask[r * 4 + w];
                while (bits) {   // uniform across warp -> no divergence
                    int j = (w << 5) + (__ffs(bits) - 1);
                    bits &= bits - 1;
                    const float* tr = sT + j * STS + lane;
                    s0 += tr[0];
                    s1 += tr[32];
                    s2 += tr[64];
                    s3 += tr[96];
                }
            }
            float di = sDinv[r];
            float o[4] = {fmaf(di, s0, bq[0]), fmaf(di, s1, bq[1]),
                          fmaf(di, s2, bq[2]), fmaf(di, s3, bq[3])};
            if (ELU) {
#pragma unroll
                for (int q = 0; q < 4; ++q) o[q] = o[q] > 0.f ? o[q] : expm1f(o[q]);
            }
            float* orow = Hout + ((size_t)b * NN + r) * FOUT + ch * 128 + lane;
            orow[0]  = o[0];
            orow[32] = o[1];
            orow[64] = o[2];
            orow[96] = o[3];
        }
        __syncthreads();
    }
}

// ---------------------------------------------------------------------------
extern "C" void kernel_launch(void* const* d_in, const int* in_sizes, int n_in,
                              void* d_out, int out_size) {
    const float* x   = (const float*)d_in[0];
    const float* adj = (const float*)d_in[1];
    const float* W1  = (const float*)d_in[2];
    const float* b1  = (const float*)d_in[3];
    const float* W2  = (const float*)d_in[4];
    const float* b2  = (const float*)d_in[5];
    const float* W3  = (const float*)d_in[6];
    const float* b3  = (const float*)d_in[7];
    float* out = (float*)d_out;

    void* hp = nullptr;
    cudaGetSymbolAddress(&hp, g_H);
    float* H = (float*)hp;

    const int SM1 = (NN * (128 + 4) + NN * (128 + 4) + 16 * 128) * 4 + NN * 4 * 4 + NN * 4; // 145920
    const int SM2 = (NN * (256 + 4) + NN * (128 + 4) + 16 * 128) * 4 + NN * 4 * 4 + NN * 4; // 211456

    cudaFuncSetAttribute(gcn_layer<128, 256, true>,  cudaFuncAttributeMaxDynamicSharedMemorySize, SM1);
    cudaFuncSetAttribute(gcn_layer<256, 256, true>,  cudaFuncAttributeMaxDynamicSharedMemorySize, SM2);
    cudaFuncSetAttribute(gcn_layer<256, 128, false>, cudaFuncAttributeMaxDynamicSharedMemorySize, SM2);

    prep_kernel<<<NB, 256>>>(adj);
    gcn_layer<128, 256, true ><<<NB, 256, SM1>>>(x, W1, b1, H);
    gcn_layer<256, 256, true ><<<NB, 256, SM2>>>(H, W2, b2, H);
    gcn_layer<256, 128, false><<<NB, 256, SM2>>>(H, W3, b3, out);
}

// round 5
// speedup vs baseline: 2.7269x; 2.7180x over previous
#include <cuda_runtime.h>
#include <cuda_bf16.h>
#include <stdint.h>
#include <math.h>

#define NB 1024

__device__ unsigned g_mask[NB * 512];
__device__ float    g_dinv[NB * 128];
__device__ __align__(16) __nv_bfloat16 g_Wh[131072];  // W1|W2|W3 row-major [FIN][FOUT], hi
__device__ __align__(16) __nv_bfloat16 g_Wl[131072];  // lo residuals

// ---- smem layout (bytes) ----
#define OFF_BIAS 0
#define OFF_DINV 1024
#define OFF_MB   1536
#define OFF_MSK  3584        // mask bf16 [128][136]
#define OFF_HHI  38400       // H/T hi  bf16 [128][264]
#define OFF_HLO  105984      // H/T lo
#define OFF_W    173568      // 2 x (Whi[16][264] + Wlo[16][264])
#define WBUF     16896
#define WLO      8448
#define SMEM_SZ  207360
#define SH 264
#define SM 136
#define SW 264

__device__ __forceinline__ uint32_t s2u(const void* p) {
    uint32_t a;
    asm("{ .reg .u64 t; cvta.to.shared.u64 t, %1; cvt.u32.u64 %0, t; }" : "=r"(a) : "l"(p));
    return a;
}
__device__ __forceinline__ unsigned pk(float a, float b) {   // lo=a, hi=b
    unsigned r;
    asm("cvt.rn.bf16x2.f32 %0, %1, %2;" : "=r"(r) : "f"(b), "f"(a));
    return r;
}
__device__ __forceinline__ float rlo(float v) {
    return v - __bfloat162float(__float2bfloat16(v));
}
__device__ __forceinline__ void ldsm4(uint32_t* r, uint32_t a) {
    asm volatile("ldmatrix.sync.aligned.m8n8.x4.shared.b16 {%0,%1,%2,%3}, [%4];"
                 : "=r"(r[0]), "=r"(r[1]), "=r"(r[2]), "=r"(r[3]) : "r"(a));
}
__device__ __forceinline__ void ldsm4t(uint32_t* r, uint32_t a) {
    asm volatile("ldmatrix.sync.aligned.m8n8.x4.trans.shared.b16 {%0,%1,%2,%3}, [%4];"
                 : "=r"(r[0]), "=r"(r[1]), "=r"(r[2]), "=r"(r[3]) : "r"(a));
}
__device__ __forceinline__ void mma16816(float* c, const uint32_t* a, uint32_t b0, uint32_t b1) {
    asm volatile(
        "mma.sync.aligned.m16n8k16.row.col.f32.bf16.bf16.f32 "
        "{%0,%1,%2,%3}, {%4,%5,%6,%7}, {%8,%9}, {%0,%1,%2,%3};"
        : "+f"(c[0]), "+f"(c[1]), "+f"(c[2]), "+f"(c[3])
        : "r"(a[0]), "r"(a[1]), "r"(a[2]), "r"(a[3]), "r"(b0), "r"(b1));
}

// ---------------- prep: adjacency masks + dinv ----------------
__global__ __launch_bounds__(256) void prep_mask(const float* __restrict__ adj) {
    int b = blockIdx.x, warp = threadIdx.x >> 5, lane = threadIdx.x & 31;
    for (int r = warp; r < 128; r += 8) {
        const float* a = adj + ((size_t)b * 128 + r) * 128;
        unsigned m[4]; int deg = 0;
#pragma unroll
        for (int s = 0; s < 4; ++s) {
            unsigned w = __ballot_sync(0xffffffffu, a[lane + 32 * s] != 0.0f);
            if (s == (r >> 5)) w |= 1u << (r & 31);
            m[s] = w; deg += __popc(w);
        }
        if (lane == 0) {
            g_dinv[b * 128 + r] = rsqrtf((float)deg);
#pragma unroll
            for (int s = 0; s < 4; ++s) g_mask[(b * 128 + r) * 4 + s] = m[s];
        }
    }
}

// ---------------- prep: W hi/lo row-major images ----------------
__global__ __launch_bounds__(256) void prep_w(const float* __restrict__ W1,
                                              const float* __restrict__ W2,
                                              const float* __restrict__ W3) {
    int id = blockIdx.x * 256 + threadIdx.x;   // 131072
    const float* W; int FOUT, base, l;
    if (id < 32768)      { W = W1; FOUT = 256; base = 0;     l = id; }
    else if (id < 98304) { W = W2; FOUT = 256; base = 32768; l = id - 32768; }
    else                 { W = W3; FOUT = 128; base = 98304; l = id - 98304; }
    int k = l / FOUT, n = l % FOUT;
    float v = W[(size_t)k * FOUT + n];
    __nv_bfloat16 h = __float2bfloat16(v);
    g_Wh[base + l] = h;
    g_Wl[base + l] = __float2bfloat16(v - __bfloat162float(h));
}

// ---------------- one layer ----------------
template <int FIN, int FOUT, bool ELU, bool LAST>
__device__ __forceinline__ void layer(char* smem, uint32_t sb, const float* __restrict__ bias,
                                      int wbase, float* __restrict__ outg, int b) {
    const int tid = threadIdx.x, lane = tid & 31, wid = tid >> 5;
    const int wm = wid >> 1, wn = wid & 1;
    constexpr int NW = FOUT / 2, NT16 = NW / 16, NT8 = NW / 8, KS = FIN / 16;

    float* sBias = (float*)(smem + OFF_BIAS);
    const float* sDinv = (const float*)(smem + OFF_DINV);
    for (int n = tid; n < FOUT; n += 512) sBias[n] = bias[n];

    float acc[NT8][4];
#pragma unroll
    for (int i = 0; i < NT8; ++i)
#pragma unroll
        for (int q = 0; q < 4; ++q) acc[i][q] = 0.0f;

    // ---- GEMM1: T = H @ W  (3 hi/lo products), W k-tiles double-buffered ----
    auto stage = [&](int k, int buf) {
        const int cnt = 16 * FOUT / 8;
        if (tid < cnt) {
            int r = tid / (FOUT / 8), c8 = (tid % (FOUT / 8)) * 8;
            uint4 h = *(const uint4*)(g_Wh + wbase + (k * 16 + r) * FOUT + c8);
            uint4 l = *(const uint4*)(g_Wl + wbase + (k * 16 + r) * FOUT + c8);
            *(uint4*)(smem + OFF_W + buf * WBUF + (r * SW + c8) * 2) = h;
            *(uint4*)(smem + OFF_W + buf * WBUF + WLO + (r * SW + c8) * 2) = l;
        }
    };
    stage(0, 0);
    __syncthreads();

    const uint32_t aRow  = (uint32_t)(wm * 16 + (lane & 15));
    const uint32_t aCol8 = (uint32_t)((lane >> 4) * 8);
    const uint32_t bRow  = (uint32_t)((lane & 7) + ((lane >> 3) & 1) * 8);
    const uint32_t bCol8 = (uint32_t)((lane >> 4) * 8);

    for (int k = 0; k < KS; ++k) {
        if (k + 1 < KS) stage(k + 1, (k + 1) & 1);
        uint32_t ah[4], al[4];
        uint32_t aoff = (aRow * SH + k * 16 + aCol8) * 2;
        ldsm4(ah, sb + OFF_HHI + aoff);
        ldsm4(al, sb + OFF_HLO + aoff);
        uint32_t wb = sb + OFF_W + (k & 1) * WBUF;
#pragma unroll
        for (int t = 0; t < NT16; ++t) {
            uint32_t boff = (bRow * SW + wn * NW + t * 16 + bCol8) * 2;
            uint32_t bh[4], bl[4];
            ldsm4t(bh, wb + boff);
            ldsm4t(bl, wb + WLO + boff);
            mma16816(acc[2 * t], ah, bh[0], bh[1]);
            mma16816(acc[2 * t], al, bh[0], bh[1]);
            mma16816(acc[2 * t], ah, bl[0], bl[1]);
            mma16816(acc[2 * t + 1], ah, bh[2], bh[3]);
            mma16816(acc[2 * t + 1], al, bh[2], bh[3]);
            mma16816(acc[2 * t + 1], ah, bl[2], bl[3]);
        }
        __syncthreads();
    }

    // ---- epilogue1: write T * dinv_row (hi/lo) into H buffers ----
    {
        int r0 = wm * 16 + (lane >> 2), r1 = r0 + 8;
        float d0 = sDinv[r0], d1 = sDinv[r1];
#pragma unroll
        for (int i = 0; i < NT8; ++i) {
            int col = wn * NW + i * 8 + (lane & 3) * 2;
            float v00 = acc[i][0] * d0, v01 = acc[i][1] * d0;
            float v10 = acc[i][2] * d1, v11 = acc[i][3] * d1;
            *(unsigned*)(smem + OFF_HHI + (r0 * SH + col) * 2) = pk(v00, v01);
            *(unsigned*)(smem + OFF_HLO + (r0 * SH + col) * 2) = pk(rlo(v00), rlo(v01));
            *(unsigned*)(smem + OFF_HHI + (r1 * SH + col) * 2) = pk(v10, v11);
            *(unsigned*)(smem + OFF_HLO + (r1 * SH + col) * 2) = pk(rlo(v10), rlo(v11));
        }
    }
    __syncthreads();

    // ---- GEMM2: out = Mask @ T (2 products; mask exact in bf16) ----
    float ac2[NT8][4];
#pragma unroll
    for (int i = 0; i < NT8; ++i)
#pragma unroll
        for (int q = 0; q < 4; ++q) ac2[i][q] = 0.0f;

    for (int k = 0; k < 8; ++k) {
        uint32_t am[4];
        ldsm4(am, sb + OFF_MSK + (aRow * SM + k * 16 + aCol8) * 2);
#pragma unroll
        for (int t = 0; t < NT16; ++t) {
            uint32_t boff = ((k * 16 + bRow) * SH + wn * NW + t * 16 + bCol8) * 2;
            uint32_t th[4], tl[4];
            ldsm4t(th, sb + OFF_HHI + boff);
            ldsm4t(tl, sb + OFF_HLO + boff);
            mma16816(ac2[2 * t], am, th[0], th[1]);
            mma16816(ac2[2 * t], am, tl[0], tl[1]);
            mma16816(ac2[2 * t + 1], am, th[2], th[3]);
            mma16816(ac2[2 * t + 1], am, tl[2], tl[3]);
        }
    }
    __syncthreads();

    // ---- epilogue2: *dinv_i + bias, ELU, write next-H or global out ----
    {
        int r0 = wm * 16 + (lane >> 2), r1 = r0 + 8;
        float d0 = sDinv[r0], d1 = sDinv[r1];
#pragma unroll
        for (int i = 0; i < NT8; ++i) {
            int col = wn * NW + i * 8 + (lane & 3) * 2;
            float b0v = sBias[col], b1v = sBias[col + 1];
            float v00 = fmaf(ac2[i][0], d0, b0v), v01 = fmaf(ac2[i][1], d0, b1v);
            float v10 = fmaf(ac2[i][2], d1, b0v), v11 = fmaf(ac2[i][3], d1, b1v);
            if (ELU) {
                v00 = v00 > 0.f ? v00 : expm1f(v00);
                v01 = v01 > 0.f ? v01 : expm1f(v01);
                v10 = v10 > 0.f ? v10 : expm1f(v10);
                v11 = v11 > 0.f ? v11 : expm1f(v11);
            }
            if (LAST) {
                *(float2*)(outg + ((size_t)b * 128 + r0) * 128 + col) = make_float2(v00, v01);
                *(float2*)(outg + ((size_t)b * 128 + r1) * 128 + col) = make_float2(v10, v11);
            } else {
                *(unsigned*)(smem + OFF_HHI + (r0 * SH + col) * 2) = pk(v00, v01);
                *(unsigned*)(smem + OFF_HLO + (r0 * SH + col) * 2) = pk(rlo(v00), rlo(v01));
                *(unsigned*)(smem + OFF_HHI + (r1 * SH + col) * 2) = pk(v10, v11);
                *(unsigned*)(smem + OFF_HLO + (r1 * SH + col) * 2) = pk(rlo(v10), rlo(v11));
            }
        }
    }
    __syncthreads();
}

// ---------------- fused kernel ----------------
__global__ void __launch_bounds__(512, 1) gcn_fused(
    const float* __restrict__ x,
    const float* __restrict__ b1, const float* __restrict__ b2,
    const float* __restrict__ b3, float* __restrict__ out) {
    extern __shared__ char smem[];
    const uint32_t sb = s2u(smem);
    const int b = blockIdx.x, tid = threadIdx.x;

    ((unsigned*)(smem + OFF_MB))[tid] = g_mask[(size_t)b * 512 + tid];
    if (tid < 128) ((float*)(smem + OFF_DINV))[tid] = g_dinv[b * 128 + tid];
    __syncthreads();

    // binary mask -> bf16 matrix [128][136]
    const unsigned* mb = (const unsigned*)(smem + OFF_MB);
    for (int idx = tid; idx < 8192; idx += 512) {
        int i = idx >> 6, j2 = (idx & 63) * 2;
        unsigned w = mb[i * 4 + (j2 >> 5)];
        float f0 = (w >> (j2 & 31)) & 1u ? 1.f : 0.f;
        float f1 = (w >> ((j2 + 1) & 31)) & 1u ? 1.f : 0.f;
        *(unsigned*)(smem + OFF_MSK + (i * SM + j2) * 2) = pk(f0, f1);
    }
    // stage x as hi/lo
    const float* xb = x + (size_t)b * 16384;
    for (int idx = tid; idx < 8192; idx += 512) {
        int r = idx >> 6, c2 = (idx & 63) * 2;
        float v0 = xb[r * 128 + c2], v1 = xb[r * 128 + c2 + 1];
        *(unsigned*)(smem + OFF_HHI + (r * SH + c2) * 2) = pk(v0, v1);
        *(unsigned*)(smem + OFF_HLO + (r * SH + c2) * 2) = pk(rlo(v0), rlo(v1));
    }
    __syncthreads();

    layer<128, 256, true,  false>(smem, sb, b1, 0,     out, b);
    layer<256, 256, true,  false>(smem, sb, b2, 32768, out, b);
    layer<256, 128, false, true >(smem, sb, b3, 98304, out, b);
}

// ---------------------------------------------------------------------------
extern "C" void kernel_launch(void* const* d_in, const int* in_sizes, int n_in,
                              void* d_out, int out_size) {
    const float* x   = (const float*)d_in[0];
    const float* adj = (const float*)d_in[1];
    const float* W1  = (const float*)d_in[2];
    const float* b1  = (const float*)d_in[3];
    const float* W2  = (const float*)d_in[4];
    const float* b2  = (const float*)d_in[5];
    const float* W3  = (const float*)d_in[6];
    const float* b3  = (const float*)d_in[7];
    float* out = (float*)d_out;

    cudaFuncSetAttribute(gcn_fused, cudaFuncAttributeMaxDynamicSharedMemorySize, SMEM_SZ);
    prep_mask<<<NB, 256>>>(adj);
    prep_w<<<512, 256>>>(W1, W2, W3);
    gcn_fused<<<NB, 512, SMEM_SZ>>>(x, b1, b2, b3, out);
}

// round 6
// speedup vs baseline: 2.8283x; 1.0372x over previous
#include <cuda_runtime.h>
#include <cuda_bf16.h>
#include <stdint.h>
#include <math.h>

#define NB 1024

__device__ __align__(16) __nv_bfloat16 g_Wh[131072];  // W1|W2|W3 row-major [FIN][FOUT], hi
__device__ __align__(16) __nv_bfloat16 g_Wl[131072];  // lo residuals

// ---- smem layout (bytes) ----
#define OFF_BIAS 0
#define OFF_DINV 1024
#define OFF_MB   1536
#define OFF_MSK  3584        // mask bf16 [128][136]
#define OFF_HHI  38400       // H/T hi  bf16 [128][264]
#define OFF_HLO  105984      // H/T lo
#define OFF_W    173568      // 2 x (Whi[16][264] + Wlo[16][264])
#define WBUF     16896
#define WLO      8448
#define SMEM_SZ  207360
#define SH 264
#define SM 136
#define SW 264

__device__ __forceinline__ uint32_t s2u(const void* p) {
    uint32_t a;
    asm("{ .reg .u64 t; cvta.to.shared.u64 t, %1; cvt.u32.u64 %0, t; }" : "=r"(a) : "l"(p));
    return a;
}
__device__ __forceinline__ unsigned pk(float a, float b) {   // lo=a, hi=b
    unsigned r;
    asm("cvt.rn.bf16x2.f32 %0, %1, %2;" : "=r"(r) : "f"(b), "f"(a));
    return r;
}
__device__ __forceinline__ float rlo(float v) {
    return v - __bfloat162float(__float2bfloat16(v));
}
__device__ __forceinline__ void ldsm4(uint32_t* r, uint32_t a) {
    asm volatile("ldmatrix.sync.aligned.m8n8.x4.shared.b16 {%0,%1,%2,%3}, [%4];"
                 : "=r"(r[0]), "=r"(r[1]), "=r"(r[2]), "=r"(r[3]) : "r"(a));
}
__device__ __forceinline__ void ldsm4t(uint32_t* r, uint32_t a) {
    asm volatile("ldmatrix.sync.aligned.m8n8.x4.trans.shared.b16 {%0,%1,%2,%3}, [%4];"
                 : "=r"(r[0]), "=r"(r[1]), "=r"(r[2]), "=r"(r[3]) : "r"(a));
}
__device__ __forceinline__ void mma16816(float* c, const uint32_t* a, uint32_t b0, uint32_t b1) {
    asm volatile(
        "mma.sync.aligned.m16n8k16.row.col.f32.bf16.bf16.f32 "
        "{%0,%1,%2,%3}, {%4,%5,%6,%7}, {%8,%9}, {%0,%1,%2,%3};"
        : "+f"(c[0]), "+f"(c[1]), "+f"(c[2]), "+f"(c[3])
        : "r"(a[0]), "r"(a[1]), "r"(a[2]), "r"(a[3]), "r"(b0), "r"(b1));
}
__device__ __forceinline__ void cp16(uint32_t s, const void* g) {
    unsigned long long ga = (unsigned long long)__cvta_generic_to_global(g);
    asm volatile("cp.async.ca.shared.global [%0], [%1], 16;" :: "r"(s), "l"(ga) : "memory");
}
#define CP_COMMIT asm volatile("cp.async.commit_group;" ::: "memory")
#define CP_WAIT0  asm volatile("cp.async.wait_group 0;" ::: "memory")

// ---------------- prep: W hi/lo row-major images ----------------
__global__ __launch_bounds__(256) void prep_w(const float* __restrict__ W1,
                                              const float* __restrict__ W2,
                                              const float* __restrict__ W3) {
    int id = blockIdx.x * 256 + threadIdx.x;   // 131072
    const float* W; int FOUT, base, l;
    if (id < 32768)      { W = W1; FOUT = 256; base = 0;     l = id; }
    else if (id < 98304) { W = W2; FOUT = 256; base = 32768; l = id - 32768; }
    else                 { W = W3; FOUT = 128; base = 98304; l = id - 98304; }
    int k = l / FOUT, n = l % FOUT;
    float v = W[(size_t)k * FOUT + n];
    __nv_bfloat16 h = __float2bfloat16(v);
    g_Wh[base + l] = h;
    g_Wl[base + l] = __float2bfloat16(v - __bfloat162float(h));
}

// ---------------- one layer ----------------
template <int FIN, int FOUT, bool ELU, bool LAST>
__device__ __forceinline__ void layer(char* smem, uint32_t sb, const float* __restrict__ bias,
                                      int wbase, float* __restrict__ outg, int b) {
    const int tid = threadIdx.x, lane = tid & 31, wid = tid >> 5;
    const int wm = wid >> 2, wn = wid & 3;               // 4 x 4 warp grid
    constexpr int NWN = FOUT / 4, NT16 = NWN / 16, NT8 = NWN / 8, KS = FIN / 16;

    float* sBias = (float*)(smem + OFF_BIAS);
    const float* sDinv = (const float*)(smem + OFF_DINV);
    for (int n = tid; n < FOUT; n += 512) sBias[n] = bias[n];

    float acc[2][NT8][4];
#pragma unroll
    for (int m = 0; m < 2; ++m)
#pragma unroll
        for (int i = 0; i < NT8; ++i)
#pragma unroll
            for (int q = 0; q < 4; ++q) acc[m][i][q] = 0.0f;

    // ---- GEMM1: T = H @ W  (3 hi/lo products), cp.async double-buffered W ----
    auto stage = [&](int k, int buf) {
        const int cnt = 16 * FOUT / 8;
        if (tid < cnt) {
            int r = tid / (FOUT / 8), c8 = (tid % (FOUT / 8)) * 8;
            size_t go = (size_t)wbase + (size_t)(k * 16 + r) * FOUT + c8;
            uint32_t sh_ = sb + OFF_W + buf * WBUF + (uint32_t)(r * SW + c8) * 2;
            cp16(sh_, g_Wh + go);
            cp16(sh_ + WLO, g_Wl + go);
        }
    };
    stage(0, 0);
    CP_COMMIT;
    CP_WAIT0;
    __syncthreads();

    const uint32_t aRow  = (uint32_t)(wm * 32 + (lane & 15));
    const uint32_t aCol8 = (uint32_t)((lane >> 4) * 8);
    const uint32_t bRow  = (uint32_t)((lane & 7) + ((lane >> 3) & 1) * 8);
    const uint32_t bCol8 = (uint32_t)((lane >> 4) * 8);

    for (int k = 0; k < KS; ++k) {
        if (k + 1 < KS) stage(k + 1, (k + 1) & 1);
        CP_COMMIT;
        uint32_t ah[2][4], al[2][4];
#pragma unroll
        for (int m = 0; m < 2; ++m) {
            uint32_t aoff = ((aRow + 16 * m) * SH + k * 16 + aCol8) * 2;
            ldsm4(ah[m], sb + OFF_HHI + aoff);
            ldsm4(al[m], sb + OFF_HLO + aoff);
        }
        uint32_t wb = sb + OFF_W + (k & 1) * WBUF;
#pragma unroll
        for (int t = 0; t < NT16; ++t) {
            uint32_t boff = (bRow * SW + wn * NWN + t * 16 + bCol8) * 2;
            uint32_t bh[4], bl[4];
            ldsm4t(bh, wb + boff);
            ldsm4t(bl, wb + WLO + boff);
#pragma unroll
            for (int m = 0; m < 2; ++m) {
                mma16816(acc[m][2 * t], ah[m], bh[0], bh[1]);
                mma16816(acc[m][2 * t], al[m], bh[0], bh[1]);
                mma16816(acc[m][2 * t], ah[m], bl[0], bl[1]);
                mma16816(acc[m][2 * t + 1], ah[m], bh[2], bh[3]);
                mma16816(acc[m][2 * t + 1], al[m], bh[2], bh[3]);
                mma16816(acc[m][2 * t + 1], ah[m], bl[2], bl[3]);
            }
        }
        CP_WAIT0;
        __syncthreads();
    }

    // ---- epilogue1: write T * dinv_row (hi/lo) into H buffers ----
#pragma unroll
    for (int m = 0; m < 2; ++m) {
        int r0 = wm * 32 + m * 16 + (lane >> 2), r1 = r0 + 8;
        float d0 = sDinv[r0], d1 = sDinv[r1];
#pragma unroll
        for (int i = 0; i < NT8; ++i) {
            int col = wn * NWN + i * 8 + (lane & 3) * 2;
            float v00 = acc[m][i][0] * d0, v01 = acc[m][i][1] * d0;
            float v10 = acc[m][i][2] * d1, v11 = acc[m][i][3] * d1;
            *(unsigned*)(smem + OFF_HHI + (r0 * SH + col) * 2) = pk(v00, v01);
            *(unsigned*)(smem + OFF_HLO + (r0 * SH + col) * 2) = pk(rlo(v00), rlo(v01));
            *(unsigned*)(smem + OFF_HHI + (r1 * SH + col) * 2) = pk(v10, v11);
            *(unsigned*)(smem + OFF_HLO + (r1 * SH + col) * 2) = pk(rlo(v10), rlo(v11));
        }
    }
    __syncthreads();

    // ---- GEMM2: out = Mask @ T (2 products; mask exact in bf16) ----
    float ac2[2][NT8][4];
#pragma unroll
    for (int m = 0; m < 2; ++m)
#pragma unroll
        for (int i = 0; i < NT8; ++i)
#pragma unroll
            for (int q = 0; q < 4; ++q) ac2[m][i][q] = 0.0f;

    for (int k = 0; k < 8; ++k) {
        uint32_t am[2][4];
#pragma unroll
        for (int m = 0; m < 2; ++m)
            ldsm4(am[m], sb + OFF_MSK + ((aRow + 16 * m) * SM + k * 16 + aCol8) * 2);
#pragma unroll
        for (int t = 0; t < NT16; ++t) {
            uint32_t boff = ((k * 16 + bRow) * SH + wn * NWN + t * 16 + bCol8) * 2;
            uint32_t th[4], tl[4];
            ldsm4t(th, sb + OFF_HHI + boff);
            ldsm4t(tl, sb + OFF_HLO + boff);
#pragma unroll
            for (int m = 0; m < 2; ++m) {
                mma16816(ac2[m][2 * t], am[m], th[0], th[1]);
                mma16816(ac2[m][2 * t], am[m], tl[0], tl[1]);
                mma16816(ac2[m][2 * t + 1], am[m], th[2], th[3]);
                mma16816(ac2[m][2 * t + 1], am[m], tl[2], tl[3]);
            }
        }
    }
    __syncthreads();

    // ---- epilogue2: *dinv_i + bias, ELU, write next-H or global out ----
#pragma unroll
    for (int m = 0; m < 2; ++m) {
        int r0 = wm * 32 + m * 16 + (lane >> 2), r1 = r0 + 8;
        float d0 = sDinv[r0], d1 = sDinv[r1];
#pragma unroll
        for (int i = 0; i < NT8; ++i) {
            int col = wn * NWN + i * 8 + (lane & 3) * 2;
            float b0v = sBias[col], b1v = sBias[col + 1];
            float v00 = fmaf(ac2[m][i][0], d0, b0v), v01 = fmaf(ac2[m][i][1], d0, b1v);
            float v10 = fmaf(ac2[m][i][2], d1, b0v), v11 = fmaf(ac2[m][i][3], d1, b1v);
            if (ELU) {
                v00 = v00 > 0.f ? v00 : expm1f(v00);
                v01 = v01 > 0.f ? v01 : expm1f(v01);
                v10 = v10 > 0.f ? v10 : expm1f(v10);
                v11 = v11 > 0.f ? v11 : expm1f(v11);
            }
            if (LAST) {
                *(float2*)(outg + ((size_t)b * 128 + r0) * 128 + col) = make_float2(v00, v01);
                *(float2*)(outg + ((size_t)b * 128 + r1) * 128 + col) = make_float2(v10, v11);
            } else {
                *(unsigned*)(smem + OFF_HHI + (r0 * SH + col) * 2) = pk(v00, v01);
                *(unsigned*)(smem + OFF_HLO + (r0 * SH + col) * 2) = pk(rlo(v00), rlo(v01));
                *(unsigned*)(smem + OFF_HHI + (r1 * SH + col) * 2) = pk(v10, v11);
                *(unsigned*)(smem + OFF_HLO + (r1 * SH + col) * 2) = pk(rlo(v10), rlo(v11));
            }
        }
    }
    __syncthreads();
}

// ---------------- fused kernel (mask build fused in) ----------------
__global__ void __launch_bounds__(512, 1) gcn_fused(
    const float* __restrict__ x, const float* __restrict__ adj,
    const float* __restrict__ b1, const float* __restrict__ b2,
    const float* __restrict__ b3, float* __restrict__ out) {
    extern __shared__ char smem[];
    const uint32_t sb = s2u(smem);
    const int b = blockIdx.x, tid = threadIdx.x;
    const int warp = tid >> 5, lane = tid & 31;

    // build 128-bit row masks + dinv from adj (ballot), directly in smem
    unsigned* sMB = (unsigned*)(smem + OFF_MB);
    float* sDinv = (float*)(smem + OFF_DINV);
    const float* ab = adj + (size_t)b * 16384;
    for (int r = warp; r < 128; r += 16) {
        const float* a = ab + r * 128;
        unsigned m[4]; int deg = 0;
#pragma unroll
        for (int s = 0; s < 4; ++s) {
            unsigned w = __ballot_sync(0xffffffffu, a[lane + 32 * s] != 0.0f);
            if (s == (r >> 5)) w |= 1u << (r & 31);
            m[s] = w; deg += __popc(w);
        }
        if (lane == 0) {
            sDinv[r] = rsqrtf((float)deg);
#pragma unroll
            for (int s = 0; s < 4; ++s) sMB[r * 4 + s] = m[s];
        }
    }
    __syncthreads();

    // binary mask -> bf16 matrix [128][136]
    for (int idx = tid; idx < 8192; idx += 512) {
        int i = idx >> 6, j2 = (idx & 63) * 2;
        unsigned w = sMB[i * 4 + (j2 >> 5)];
        float f0 = (w >> (j2 & 31)) & 1u ? 1.f : 0.f;
        float f1 = (w >> ((j2 + 1) & 31)) & 1u ? 1.f : 0.f;
        *(unsigned*)(smem + OFF_MSK + (i * SM + j2) * 2) = pk(f0, f1);
    }
    // stage x as hi/lo
    const float* xb = x + (size_t)b * 16384;
    for (int idx = tid; idx < 8192; idx += 512) {
        int r = idx >> 6, c2 = (idx & 63) * 2;
        float v0 = xb[r * 128 + c2], v1 = xb[r * 128 + c2 + 1];
        *(unsigned*)(smem + OFF_HHI + (r * SH + c2) * 2) = pk(v0, v1);
        *(unsigned*)(smem + OFF_HLO + (r * SH + c2) * 2) = pk(rlo(v0), rlo(v1));
    }
    __syncthreads();

    layer<128, 256, true,  false>(smem, sb, b1, 0,     out, b);
    layer<256, 256, true,  false>(smem, sb, b2, 32768, out, b);
    layer<256, 128, false, true >(smem, sb, b3, 98304, out, b);
}

// ---------------------------------------------------------------------------
extern "C" void kernel_launch(void* const* d_in, const int* in_sizes, int n_in,
                              void* d_out, int out_size) {
    const float* x   = (const float*)d_in[0];
    const float* adj = (const float*)d_in[1];
    const float* W1  = (const float*)d_in[2];
    const float* b1  = (const float*)d_in[3];
    const float* W2  = (const float*)d_in[4];
    const float* b2  = (const float*)d_in[5];
    const float* W3  = (const float*)d_in[6];
    const float* b3  = (const float*)d_in[7];
    float* out = (float*)d_out;

    cudaFuncSetAttribute(gcn_fused, cudaFuncAttributeMaxDynamicSharedMemorySize, SMEM_SZ);
    prep_w<<<512, 256>>>(W1, W2, W3);
    gcn_fused<<<NB, 512, SMEM_SZ>>>(x, adj, b1, b2, b3, out);
}

// round 7
// speedup vs baseline: 3.3015x; 1.1673x over previous
#include <cuda_runtime.h>
#include <cuda_fp16.h>
#include <stdint.h>
#include <math.h>

#define NB 1024

__device__ __align__(16) __half g_Wh[131072];  // W1|W2|W3 row-major [FIN][FOUT], fp16

// ---- smem layout (bytes) ----
#define OFF_BIAS 0
#define OFF_DINV 1024
#define OFF_MB   1536        // bitmask [128][4] words
#define OFF_HHI  3584        // H/T hi  fp16 [128][264]
#define OFF_HLO  71168       // H/T lo
#define OFF_W    138752      // 2 x Whi[16][264]
#define WBUF     8448
#define SMEM_SZ  155648
#define SH 264
#define SW 264

__device__ __forceinline__ uint32_t s2u(const void* p) {
    uint32_t a;
    asm("{ .reg .u64 t; cvta.to.shared.u64 t, %1; cvt.u32.u64 %0, t; }" : "=r"(a) : "l"(p));
    return a;
}
__device__ __forceinline__ unsigned pk(float a, float b) {   // lo=a, hi=b
    __half2 h = __floats2half2_rn(a, b);
    return *(unsigned*)&h;
}
__device__ __forceinline__ float rlo(float v) {
    return v - __half2float(__float2half_rn(v));
}
__device__ __forceinline__ void ldsm4(uint32_t* r, uint32_t a) {
    asm volatile("ldmatrix.sync.aligned.m8n8.x4.shared.b16 {%0,%1,%2,%3}, [%4];"
                 : "=r"(r[0]), "=r"(r[1]), "=r"(r[2]), "=r"(r[3]) : "r"(a));
}
__device__ __forceinline__ void ldsm4t(uint32_t* r, uint32_t a) {
    asm volatile("ldmatrix.sync.aligned.m8n8.x4.trans.shared.b16 {%0,%1,%2,%3}, [%4];"
                 : "=r"(r[0]), "=r"(r[1]), "=r"(r[2]), "=r"(r[3]) : "r"(a));
}
__device__ __forceinline__ void mma16816(float* c, const uint32_t* a, uint32_t b0, uint32_t b1) {
    asm volatile(
        "mma.sync.aligned.m16n8k16.row.col.f32.f16.f16.f32 "
        "{%0,%1,%2,%3}, {%4,%5,%6,%7}, {%8,%9}, {%0,%1,%2,%3};"
        : "+f"(c[0]), "+f"(c[1]), "+f"(c[2]), "+f"(c[3])
        : "r"(a[0]), "r"(a[1]), "r"(a[2]), "r"(a[3]), "r"(b0), "r"(b1));
}
__device__ __forceinline__ void cp16(uint32_t s, const void* g) {
    unsigned long long ga = (unsigned long long)__cvta_generic_to_global(g);
    asm volatile("cp.async.ca.shared.global [%0], [%1], 16;" :: "r"(s), "l"(ga) : "memory");
}
#define CP_COMMIT asm volatile("cp.async.commit_group;" ::: "memory")
#define CP_WAIT0  asm volatile("cp.async.wait_group 0;" ::: "memory")

// ---------------- prep: W fp16 row-major images ----------------
__global__ __launch_bounds__(256) void prep_w(const float* __restrict__ W1,
                                              const float* __restrict__ W2,
                                              const float* __restrict__ W3) {
    int id = blockIdx.x * 256 + threadIdx.x;   // 131072
    const float* W; int FOUT, base, l;
    if (id < 32768)      { W = W1; FOUT = 256; base = 0;     l = id; }
    else if (id < 98304) { W = W2; FOUT = 256; base = 32768; l = id - 32768; }
    else                 { W = W3; FOUT = 128; base = 98304; l = id - 98304; }
    g_Wh[base + l] = __float2half_rn(W[l]);
}

// ---------------- one layer ----------------
template <int FIN, int FOUT, bool ELU, bool LAST>
__device__ __forceinline__ void layer(char* smem, uint32_t sb, const float* __restrict__ bias,
                                      int wbase, float* __restrict__ outg, int b) {
    const int tid = threadIdx.x, lane = tid & 31, wid = tid >> 5;
    const int wm = wid >> 2, wn = wid & 3;               // 4 x 4 warp grid
    constexpr int NWN = FOUT / 4, NT16 = NWN / 16, NT8 = NWN / 8, KS = FIN / 16;

    float* sBias = (float*)(smem + OFF_BIAS);
    const float* sDinv = (const float*)(smem + OFF_DINV);
    const unsigned* sMB = (const unsigned*)(smem + OFF_MB);
    for (int n = tid; n < FOUT; n += 512) sBias[n] = bias[n];

    float acc[2][NT8][4];
#pragma unroll
    for (int m = 0; m < 2; ++m)
#pragma unroll
        for (int i = 0; i < NT8; ++i)
#pragma unroll
            for (int q = 0; q < 4; ++q) acc[m][i][q] = 0.0f;

    // ---- GEMM1: T = H @ W  (2 products: Hhi*W + Hlo*W), cp.async W ring ----
    auto stage = [&](int k, int buf) {
        const int cnt = 16 * FOUT / 8;
        if (tid < cnt) {
            int r = tid / (FOUT / 8), c8 = (tid % (FOUT / 8)) * 8;
            size_t go = (size_t)wbase + (size_t)(k * 16 + r) * FOUT + c8;
            cp16(sb + OFF_W + buf * WBUF + (uint32_t)(r * SW + c8) * 2, g_Wh + go);
        }
    };
    stage(0, 0);
    CP_COMMIT;
    CP_WAIT0;
    __syncthreads();

    const uint32_t aRow  = (uint32_t)(wm * 32 + (lane & 15));
    const uint32_t aCol8 = (uint32_t)((lane >> 4) * 8);
    const uint32_t bRow  = (uint32_t)((lane & 7) + ((lane >> 3) & 1) * 8);
    const uint32_t bCol8 = (uint32_t)((lane >> 4) * 8);

    for (int k = 0; k < KS; ++k) {
        if (k + 1 < KS) stage(k + 1, (k + 1) & 1);
        CP_COMMIT;
        uint32_t ah[2][4], al[2][4];
#pragma unroll
        for (int m = 0; m < 2; ++m) {
            uint32_t aoff = ((aRow + 16 * m) * SH + k * 16 + aCol8) * 2;
            ldsm4(ah[m], sb + OFF_HHI + aoff);
            ldsm4(al[m], sb + OFF_HLO + aoff);
        }
        uint32_t wb = sb + OFF_W + (k & 1) * WBUF;
#pragma unroll
        for (int t = 0; t < NT16; ++t) {
            uint32_t boff = (bRow * SW + wn * NWN + t * 16 + bCol8) * 2;
            uint32_t bh[4];
            ldsm4t(bh, wb + boff);
#pragma unroll
            for (int m = 0; m < 2; ++m) {
                mma16816(acc[m][2 * t], ah[m], bh[0], bh[1]);
                mma16816(acc[m][2 * t], al[m], bh[0], bh[1]);
                mma16816(acc[m][2 * t + 1], ah[m], bh[2], bh[3]);
                mma16816(acc[m][2 * t + 1], al[m], bh[2], bh[3]);
            }
        }
        CP_WAIT0;
        __syncthreads();
    }

    // ---- epilogue1: write T * dinv_row (hi/lo) into H buffers ----
#pragma unroll
    for (int m = 0; m < 2; ++m) {
        int r0 = wm * 32 + m * 16 + (lane >> 2), r1 = r0 + 8;
        float d0 = sDinv[r0], d1 = sDinv[r1];
#pragma unroll
        for (int i = 0; i < NT8; ++i) {
            int col = wn * NWN + i * 8 + (lane & 3) * 2;
            float v00 = acc[m][i][0] * d0, v01 = acc[m][i][1] * d0;
            float v10 = acc[m][i][2] * d1, v11 = acc[m][i][3] * d1;
            *(unsigned*)(smem + OFF_HHI + (r0 * SH + col) * 2) = pk(v00, v01);
            *(unsigned*)(smem + OFF_HLO + (r0 * SH + col) * 2) = pk(rlo(v00), rlo(v01));
            *(unsigned*)(smem + OFF_HHI + (r1 * SH + col) * 2) = pk(v10, v11);
            *(unsigned*)(smem + OFF_HLO + (r1 * SH + col) * 2) = pk(rlo(v10), rlo(v11));
        }
    }
    __syncthreads();

    // ---- GEMM2: out = Mask @ T (mask fragments from bitmask registers) ----
    float ac2[2][NT8][4];
#pragma unroll
    for (int m = 0; m < 2; ++m)
#pragma unroll
        for (int i = 0; i < NT8; ++i)
#pragma unroll
            for (int q = 0; q < 4; ++q) ac2[m][i][q] = 0.0f;

    unsigned mw[4][4];   // [m*2+p][kword]
#pragma unroll
    for (int m = 0; m < 2; ++m)
#pragma unroll
        for (int p = 0; p < 2; ++p) {
            int r = wm * 32 + m * 16 + p * 8 + (lane >> 2);
#pragma unroll
            for (int kw = 0; kw < 4; ++kw) mw[m * 2 + p][kw] = sMB[r * 4 + kw];
        }
    const int cbit = (lane & 3) * 2;

    for (int k = 0; k < 8; ++k) {
        uint32_t am[2][4];
#pragma unroll
        for (int m = 0; m < 2; ++m) {
            unsigned f0 = mw[m * 2 + 0][k >> 1] >> ((k & 1) * 16);
            unsigned f1 = mw[m * 2 + 1][k >> 1] >> ((k & 1) * 16);
            am[m][0] = ((f0 >> cbit) & 1u) * 0x3C00u + ((f0 >> (cbit + 1)) & 1u) * 0x3C000000u;
            am[m][1] = ((f1 >> cbit) & 1u) * 0x3C00u + ((f1 >> (cbit + 1)) & 1u) * 0x3C000000u;
            am[m][2] = ((f0 >> (cbit + 8)) & 1u) * 0x3C00u + ((f0 >> (cbit + 9)) & 1u) * 0x3C000000u;
            am[m][3] = ((f1 >> (cbit + 8)) & 1u) * 0x3C00u + ((f1 >> (cbit + 9)) & 1u) * 0x3C000000u;
        }
#pragma unroll
        for (int t = 0; t < NT16; ++t) {
            uint32_t boff = ((k * 16 + bRow) * SH + wn * NWN + t * 16 + bCol8) * 2;
            uint32_t th[4], tl[4];
            ldsm4t(th, sb + OFF_HHI + boff);
            ldsm4t(tl, sb + OFF_HLO + boff);
#pragma unroll
            for (int m = 0; m < 2; ++m) {
                mma16816(ac2[m][2 * t], am[m], th[0], th[1]);
                mma16816(ac2[m][2 * t], am[m], tl[0], tl[1]);
                mma16816(ac2[m][2 * t + 1], am[m], th[2], th[3]);
                mma16816(ac2[m][2 * t + 1], am[m], tl[2], tl[3]);
            }
        }
    }
    __syncthreads();

    // ---- epilogue2: *dinv_i + bias, ELU, write next-H or global out ----
#pragma unroll
    for (int m = 0; m < 2; ++m) {
        int r0 = wm * 32 + m * 16 + (lane >> 2), r1 = r0 + 8;
        float d0 = sDinv[r0], d1 = sDinv[r1];
#pragma unroll
        for (int i = 0; i < NT8; ++i) {
            int col = wn * NWN + i * 8 + (lane & 3) * 2;
            float b0v = sBias[col], b1v = sBias[col + 1];
            float v00 = fmaf(ac2[m][i][0], d0, b0v), v01 = fmaf(ac2[m][i][1], d0, b1v);
            float v10 = fmaf(ac2[m][i][2], d1, b0v), v11 = fmaf(ac2[m][i][3], d1, b1v);
            if (ELU) {
                v00 = v00 > 0.f ? v00 : expm1f(v00);
                v01 = v01 > 0.f ? v01 : expm1f(v01);
                v10 = v10 > 0.f ? v10 : expm1f(v10);
                v11 = v11 > 0.f ? v11 : expm1f(v11);
            }
            if (LAST) {
                *(float2*)(outg + ((size_t)b * 128 + r0) * 128 + col) = make_float2(v00, v01);
                *(float2*)(outg + ((size_t)b * 128 + r1) * 128 + col) = make_float2(v10, v11);
            } else {
                *(unsigned*)(smem + OFF_HHI + (r0 * SH + col) * 2) = pk(v00, v01);
                *(unsigned*)(smem + OFF_HLO + (r0 * SH + col) * 2) = pk(rlo(v00), rlo(v01));
                *(unsigned*)(smem + OFF_HHI + (r1 * SH + col) * 2) = pk(v10, v11);
                *(unsigned*)(smem + OFF_HLO + (r1 * SH + col) * 2) = pk(rlo(v10), rlo(v11));
            }
        }
    }
    __syncthreads();
}

// ---------------- fused kernel (mask build fused in) ----------------
__global__ void __launch_bounds__(512, 1) gcn_fused(
    const float* __restrict__ x, const float* __restrict__ adj,
    const float* __restrict__ b1, const float* __restrict__ b2,
    const float* __restrict__ b3, float* __restrict__ out) {
    extern __shared__ char smem[];
    const uint32_t sb = s2u(smem);
    const int b = blockIdx.x, tid = threadIdx.x;
    const int warp = tid >> 5, lane = tid & 31;

    // build 128-bit row masks + dinv from adj (ballot), directly in smem
    unsigned* sMB = (unsigned*)(smem + OFF_MB);
    float* sDinv = (float*)(smem + OFF_DINV);
    const float* ab = adj + (size_t)b * 16384;
    for (int r = warp; r < 128; r += 16) {
        const float* a = ab + r * 128;
        unsigned m[4]; int deg = 0;
#pragma unroll
        for (int s = 0; s < 4; ++s) {
            unsigned w = __ballot_sync(0xffffffffu, a[lane + 32 * s] != 0.0f);
            if (s == (r >> 5)) w |= 1u << (r & 31);
            m[s] = w; deg += __popc(w);
        }
        if (lane == 0) {
            sDinv[r] = rsqrtf((float)deg);
#pragma unroll
            for (int s = 0; s < 4; ++s) sMB[r * 4 + s] = m[s];
        }
    }

    // stage x as fp16 hi/lo
    const float* xb = x + (size_t)b * 16384;
    for (int idx = tid; idx < 8192; idx += 512) {
        int r = idx >> 6, c2 = (idx & 63) * 2;
        float v0 = xb[r * 128 + c2], v1 = xb[r * 128 + c2 + 1];
        *(unsigned*)(smem + OFF_HHI + (r * SH + c2) * 2) = pk(v0, v1);
        *(unsigned*)(smem + OFF_HLO + (r * SH + c2) * 2) = pk(rlo(v0), rlo(v1));
    }
    __syncthreads();

    layer<128, 256, true,  false>(smem, sb, b1, 0,     out, b);
    layer<256, 256, true,  false>(smem, sb, b2, 32768, out, b);
    layer<256, 128, false, true >(smem, sb, b3, 98304, out, b);
}

// ---------------------------------------------------------------------------
extern "C" void kernel_launch(void* const* d_in, const int* in_sizes, int n_in,
                              void* d_out, int out_size) {
    const float* x   = (const float*)d_in[0];
    const float* adj = (const float*)d_in[1];
    const float* W1  = (const float*)d_in[2];
    const float* b1  = (const float*)d_in[3];
    const float* W2  = (const float*)d_in[4];
    const float* b2  = (const float*)d_in[5];
    const float* W3  = (const float*)d_in[6];
    const float* b3  = (const float*)d_in[7];
    float* out = (float*)d_out;

    cudaFuncSetAttribute(gcn_fused, cudaFuncAttributeMaxDynamicSharedMemorySize, SMEM_SZ);
    prep_w<<<512, 256>>>(W1, W2, W3);
    gcn_fused<<<NB, 512, SMEM_SZ>>>(x, adj, b1, b2, b3, out);
}

// round 8
// speedup vs baseline: 3.5653x; 1.0799x over previous
#include <cuda_runtime.h>
#include <cuda_fp16.h>
#include <stdint.h>
#include <math.h>

#define NB 1024

__device__ __align__(16) __half g_Wh[131072];  // W1|W2|W3 row-major [FIN][FOUT], fp16

// ---- smem layout (bytes) ----
#define OFF_BIAS 0
#define OFF_DINV 1024
#define OFF_MB   1536        // bitmask [128][4] words
#define OFF_HHI  3584        // H/T hi  fp16 [128][264]
#define OFF_HLO  71168       // H lo
#define OFF_W    138752      // 2 x Whi[32][264]
#define WBUF     16896
#define SMEM_SZ  172544
#define SH 264
#define SW 264

__device__ __forceinline__ uint32_t s2u(const void* p) {
    uint32_t a;
    asm("{ .reg .u64 t; cvta.to.shared.u64 t, %1; cvt.u32.u64 %0, t; }" : "=r"(a) : "l"(p));
    return a;
}
__device__ __forceinline__ unsigned pk(float a, float b) {   // lo=a, hi=b
    __half2 h = __floats2half2_rn(a, b);
    return *(unsigned*)&h;
}
__device__ __forceinline__ float rlo(float v) {
    return v - __half2float(__float2half_rn(v));
}
__device__ __forceinline__ void ldsm4(uint32_t* r, uint32_t a) {
    asm volatile("ldmatrix.sync.aligned.m8n8.x4.shared.b16 {%0,%1,%2,%3}, [%4];"
                 : "=r"(r[0]), "=r"(r[1]), "=r"(r[2]), "=r"(r[3]) : "r"(a));
}
__device__ __forceinline__ void ldsm4t(uint32_t* r, uint32_t a) {
    asm volatile("ldmatrix.sync.aligned.m8n8.x4.trans.shared.b16 {%0,%1,%2,%3}, [%4];"
                 : "=r"(r[0]), "=r"(r[1]), "=r"(r[2]), "=r"(r[3]) : "r"(a));
}
__device__ __forceinline__ void mma16816(float* c, const uint32_t* a, uint32_t b0, uint32_t b1) {
    asm volatile(
        "mma.sync.aligned.m16n8k16.row.col.f32.f16.f16.f32 "
        "{%0,%1,%2,%3}, {%4,%5,%6,%7}, {%8,%9}, {%0,%1,%2,%3};"
        : "+f"(c[0]), "+f"(c[1]), "+f"(c[2]), "+f"(c[3])
        : "r"(a[0]), "r"(a[1]), "r"(a[2]), "r"(a[3]), "r"(b0), "r"(b1));
}
__device__ __forceinline__ void cp16(uint32_t s, const void* g) {
    unsigned long long ga = (unsigned long long)__cvta_generic_to_global(g);
    asm volatile("cp.async.ca.shared.global [%0], [%1], 16;" :: "r"(s), "l"(ga) : "memory");
}
#define CP_COMMIT asm volatile("cp.async.commit_group;" ::: "memory")
#define CP_WAIT0  asm volatile("cp.async.wait_group 0;" ::: "memory")

// ---------------- prep: W fp16 row-major images ----------------
__global__ __launch_bounds__(256) void prep_w(const float* __restrict__ W1,
                                              const float* __restrict__ W2,
                                              const float* __restrict__ W3) {
    int id = blockIdx.x * 256 + threadIdx.x;   // 131072
    const float* W; int base, l;
    if (id < 32768)      { W = W1; base = 0;     l = id; }
    else if (id < 98304) { W = W2; base = 32768; l = id - 32768; }
    else                 { W = W3; base = 98304; l = id - 98304; }
    g_Wh[base + l] = __float2half_rn(W[l]);
}

// ---------------- one layer ----------------
template <int FIN, int FOUT, bool ELU, bool LAST>
__device__ __forceinline__ void layer(char* smem, uint32_t sb, const float* __restrict__ bias,
                                      int wbase, float* __restrict__ outg, int b) {
    const int tid = threadIdx.x, lane = tid & 31, wid = tid >> 5;
    const int wm = wid >> 2, wn = wid & 3;               // 4 x 4 warp grid
    constexpr int NWN = FOUT / 4, NT16 = NWN / 16, NT8 = NWN / 8, KS32 = FIN / 32;

    float* sBias = (float*)(smem + OFF_BIAS);
    const float* sDinv = (const float*)(smem + OFF_DINV);
    const unsigned* sMB = (const unsigned*)(smem + OFF_MB);
    for (int n = tid; n < FOUT; n += 512) sBias[n] = bias[n];

    float acc[2][NT8][4];
#pragma unroll
    for (int m = 0; m < 2; ++m)
#pragma unroll
        for (int i = 0; i < NT8; ++i)
#pragma unroll
            for (int q = 0; q < 4; ++q) acc[m][i][q] = 0.0f;

    // ---- GEMM1: T = H @ W  (2 products: Hhi*W + Hlo*W), 32-row W blocks ----
    auto stage = [&](int kb, int buf) {
        const int cnt = 32 * FOUT / 8;
        for (int i = tid; i < cnt; i += 512) {
            int r = i / (FOUT / 8), c8 = (i % (FOUT / 8)) * 8;
            size_t go = (size_t)wbase + (size_t)(kb * 32 + r) * FOUT + c8;
            cp16(sb + OFF_W + buf * WBUF + (uint32_t)(r * SW + c8) * 2, g_Wh + go);
        }
    };
    stage(0, 0);
    CP_COMMIT;
    CP_WAIT0;
    __syncthreads();

    const uint32_t aRow  = (uint32_t)(wm * 32 + (lane & 15));
    const uint32_t aCol8 = (uint32_t)((lane >> 4) * 8);
    const uint32_t bRow  = (uint32_t)((lane & 7) + ((lane >> 3) & 1) * 8);
    const uint32_t bCol8 = (uint32_t)((lane >> 4) * 8);

    for (int kb = 0; kb < KS32; ++kb) {
        if (kb + 1 < KS32) stage(kb + 1, (kb + 1) & 1);
        CP_COMMIT;
        uint32_t wb = sb + OFF_W + (kb & 1) * WBUF;
#pragma unroll
        for (int ks = 0; ks < 2; ++ks) {
            const int k = kb * 2 + ks;
            uint32_t ah[2][4], al[2][4];
#pragma unroll
            for (int m = 0; m < 2; ++m) {
                uint32_t aoff = ((aRow + 16 * m) * SH + k * 16 + aCol8) * 2;
                ldsm4(ah[m], sb + OFF_HHI + aoff);
                ldsm4(al[m], sb + OFF_HLO + aoff);
            }
#pragma unroll
            for (int t = 0; t < NT16; ++t) {
                uint32_t boff = ((ks * 16 + bRow) * SW + wn * NWN + t * 16 + bCol8) * 2;
                uint32_t bh[4];
                ldsm4t(bh, wb + boff);
#pragma unroll
                for (int m = 0; m < 2; ++m) {
                    mma16816(acc[m][2 * t], ah[m], bh[0], bh[1]);
                    mma16816(acc[m][2 * t], al[m], bh[0], bh[1]);
                    mma16816(acc[m][2 * t + 1], ah[m], bh[2], bh[3]);
                    mma16816(acc[m][2 * t + 1], al[m], bh[2], bh[3]);
                }
            }
        }
        CP_WAIT0;
        __syncthreads();
    }

    // ---- epilogue1: write T * dinv_row (hi only — GEMM2 is single-product) ----
#pragma unroll
    for (int m = 0; m < 2; ++m) {
        int r0 = wm * 32 + m * 16 + (lane >> 2), r1 = r0 + 8;
        float d0 = sDinv[r0], d1 = sDinv[r1];
#pragma unroll
        for (int i = 0; i < NT8; ++i) {
            int col = wn * NWN + i * 8 + (lane & 3) * 2;
            *(unsigned*)(smem + OFF_HHI + (r0 * SH + col) * 2) =
                pk(acc[m][i][0] * d0, acc[m][i][1] * d0);
            *(unsigned*)(smem + OFF_HHI + (r1 * SH + col) * 2) =
                pk(acc[m][i][2] * d1, acc[m][i][3] * d1);
        }
    }
    __syncthreads();

    // ---- GEMM2: out = Mask @ T (mask fragments from bitmask registers) ----
    float ac2[2][NT8][4];
#pragma unroll
    for (int m = 0; m < 2; ++m)
#pragma unroll
        for (int i = 0; i < NT8; ++i)
#pragma unroll
            for (int q = 0; q < 4; ++q) ac2[m][i][q] = 0.0f;

    unsigned mw[4][4];   // [m*2+p][kword]
#pragma unroll
    for (int m = 0; m < 2; ++m)
#pragma unroll
        for (int p = 0; p < 2; ++p) {
            int r = wm * 32 + m * 16 + p * 8 + (lane >> 2);
#pragma unroll
            for (int kw = 0; kw < 4; ++kw) mw[m * 2 + p][kw] = sMB[r * 4 + kw];
        }
    const int cbit = (lane & 3) * 2;

    for (int k = 0; k < 8; ++k) {
        uint32_t am[2][4];
#pragma unroll
        for (int m = 0; m < 2; ++m) {
            unsigned f0 = mw[m * 2 + 0][k >> 1] >> ((k & 1) * 16);
            unsigned f1 = mw[m * 2 + 1][k >> 1] >> ((k & 1) * 16);
            am[m][0] = ((f0 >> cbit) & 1u) * 0x3C00u + ((f0 >> (cbit + 1)) & 1u) * 0x3C000000u;
            am[m][1] = ((f1 >> cbit) & 1u) * 0x3C00u + ((f1 >> (cbit + 1)) & 1u) * 0x3C000000u;
            am[m][2] = ((f0 >> (cbit + 8)) & 1u) * 0x3C00u + ((f0 >> (cbit + 9)) & 1u) * 0x3C000000u;
            am[m][3] = ((f1 >> (cbit + 8)) & 1u) * 0x3C00u + ((f1 >> (cbit + 9)) & 1u) * 0x3C000000u;
        }
#pragma unroll
        for (int t = 0; t < NT16; ++t) {
            uint32_t boff = ((k * 16 + bRow) * SH + wn * NWN + t * 16 + bCol8) * 2;
            uint32_t th[4];
            ldsm4t(th, sb + OFF_HHI + boff);
#pragma unroll
            for (int m = 0; m < 2; ++m) {
                mma16816(ac2[m][2 * t], am[m], th[0], th[1]);
                mma16816(ac2[m][2 * t + 1], am[m], th[2], th[3]);
            }
        }
    }
    __syncthreads();

    // ---- epilogue2: *dinv_i + bias, ELU, write next-H (hi/lo) or global out ----
#pragma unroll
    for (int m = 0; m < 2; ++m) {
        int r0 = wm * 32 + m * 16 + (lane >> 2), r1 = r0 + 8;
        float d0 = sDinv[r0], d1 = sDinv[r1];
#pragma unroll
        for (int i = 0; i < NT8; ++i) {
            int col = wn * NWN + i * 8 + (lane & 3) * 2;
            float b0v = sBias[col], b1v = sBias[col + 1];
            float v00 = fmaf(ac2[m][i][0], d0, b0v), v01 = fmaf(ac2[m][i][1], d0, b1v);
            float v10 = fmaf(ac2[m][i][2], d1, b0v), v11 = fmaf(ac2[m][i][3], d1, b1v);
            if (ELU) {
                v00 = v00 > 0.f ? v00 : expm1f(v00);
                v01 = v01 > 0.f ? v01 : expm1f(v01);
                v10 = v10 > 0.f ? v10 : expm1f(v10);
                v11 = v11 > 0.f ? v11 : expm1f(v11);
            }
            if (LAST) {
                *(float2*)(outg + ((size_t)b * 128 + r0) * 128 + col) = make_float2(v00, v01);
                *(float2*)(outg + ((size_t)b * 128 + r1) * 128 + col) = make_float2(v10, v11);
            } else {
                *(unsigned*)(smem + OFF_HHI + (r0 * SH + col) * 2) = pk(v00, v01);
                *(unsigned*)(smem + OFF_HLO + (r0 * SH + col) * 2) = pk(rlo(v00), rlo(v01));
                *(unsigned*)(smem + OFF_HHI + (r1 * SH + col) * 2) = pk(v10, v11);
                *(unsigned*)(smem + OFF_HLO + (r1 * SH + col) * 2) = pk(rlo(v10), rlo(v11));
            }
        }
    }
    __syncthreads();
}

// ---------------- fused kernel (mask build fused in) ----------------
__global__ void __launch_bounds__(512, 1) gcn_fused(
    const float* __restrict__ x, const float* __restrict__ adj,
    const float* __restrict__ b1, const float* __restrict__ b2,
    const float* __restrict__ b3, float* __restrict__ out) {
    extern __shared__ char smem[];
    const uint32_t sb = s2u(smem);
    const int b = blockIdx.x, tid = threadIdx.x;
    const int warp = tid >> 5, lane = tid & 31;

    // build 128-bit row masks + dinv from adj (ballot), directly in smem
    unsigned* sMB = (unsigned*)(smem + OFF_MB);
    float* sDinv = (float*)(smem + OFF_DINV);
    const float* ab = adj + (size_t)b * 16384;
    for (int r = warp; r < 128; r += 16) {
        const float* a = ab + r * 128;
        unsigned m[4]; int deg = 0;
#pragma unroll
        for (int s = 0; s < 4; ++s) {
            unsigned w = __ballot_sync(0xffffffffu, a[lane + 32 * s] != 0.0f);
            if (s == (r >> 5)) w |= 1u << (r & 31);
            m[s] = w; deg += __popc(w);
        }
        if (lane == 0) {
            sDinv[r] = rsqrtf((float)deg);
#pragma unroll
            for (int s = 0; s < 4; ++s) sMB[r * 4 + s] = m[s];
        }
    }

    // stage x as fp16 hi/lo
    const float* xb = x + (size_t)b * 16384;
    for (int idx = tid; idx < 8192; idx += 512) {
        int r = idx >> 6, c2 = (idx & 63) * 2;
        float v0 = xb[r * 128 + c2], v1 = xb[r * 128 + c2 + 1];
        *(unsigned*)(smem + OFF_HHI + (r * SH + c2) * 2) = pk(v0, v1);
        *(unsigned*)(smem + OFF_HLO + (r * SH + c2) * 2) = pk(rlo(v0), rlo(v1));
    }
    __syncthreads();

    layer<128, 256, true,  false>(smem, sb, b1, 0,     out, b);
    layer<256, 256, true,  false>(smem, sb, b2, 32768, out, b);
    layer<256, 128, false, true >(smem, sb, b3, 98304, out, b);
}

// ---------------------------------------------------------------------------
extern "C" void kernel_launch(void* const* d_in, const int* in_sizes, int n_in,
                              void* d_out, int out_size) {
    const float* x   = (const float*)d_in[0];
    const float* adj = (const float*)d_in[1];
    const float* W1  = (const float*)d_in[2];
    const float* b1  = (const float*)d_in[3];
    const float* W2  = (const float*)d_in[4];
    const float* b2  = (const float*)d_in[5];
    const float* W3  = (const float*)d_in[6];
    const float* b3  = (const float*)d_in[7];
    float* out = (float*)d_out;

    cudaFuncSetAttribute(gcn_fused, cudaFuncAttributeMaxDynamicSharedMemorySize, SMEM_SZ);
    prep_w<<<512, 256>>>(W1, W2, W3);
    gcn_fused<<<NB, 512, SMEM_SZ>>>(x, adj, b1, b2, b3, out);
}

// round 9
// speedup vs baseline: 4.1337x; 1.1594x over previous
#include <cuda_runtime.h>
#include <cuda_fp16.h>
#include <stdint.h>
#include <math.h>

#define NB 1024

__device__ __align__(16) __half g_Wh[131072];  // W1|W2|W3 row-major [FIN][FOUT], fp16

// ---- smem layout (bytes) ----
#define OFF_BIAS 0
#define OFF_DINV 1024
#define OFF_MB   1536        // bitmask [128][4] words
#define OFF_HHI  3584        // H/T fp16 [128][264]
#define OFF_W    71168       // 2 x Whi[32][264]
#define WBUF     16896
#define SMEM_SZ  104960
#define SH 264
#define SW 264

__device__ __forceinline__ uint32_t s2u(const void* p) {
    uint32_t a;
    asm("{ .reg .u64 t; cvta.to.shared.u64 t, %1; cvt.u32.u64 %0, t; }" : "=r"(a) : "l"(p));
    return a;
}
__device__ __forceinline__ unsigned pk(float a, float b) {   // lo=a, hi=b
    __half2 h = __floats2half2_rn(a, b);
    return *(unsigned*)&h;
}
__device__ __forceinline__ void ldsm4(uint32_t* r, uint32_t a) {
    asm volatile("ldmatrix.sync.aligned.m8n8.x4.shared.b16 {%0,%1,%2,%3}, [%4];"
                 : "=r"(r[0]), "=r"(r[1]), "=r"(r[2]), "=r"(r[3]) : "r"(a));
}
__device__ __forceinline__ void ldsm4t(uint32_t* r, uint32_t a) {
    asm volatile("ldmatrix.sync.aligned.m8n8.x4.trans.shared.b16 {%0,%1,%2,%3}, [%4];"
                 : "=r"(r[0]), "=r"(r[1]), "=r"(r[2]), "=r"(r[3]) : "r"(a));
}
__device__ __forceinline__ void mma16816(float* c, const uint32_t* a, uint32_t b0, uint32_t b1) {
    asm volatile(
        "mma.sync.aligned.m16n8k16.row.col.f32.f16.f16.f32 "
        "{%0,%1,%2,%3}, {%4,%5,%6,%7}, {%8,%9}, {%0,%1,%2,%3};"
        : "+f"(c[0]), "+f"(c[1]), "+f"(c[2]), "+f"(c[3])
        : "r"(a[0]), "r"(a[1]), "r"(a[2]), "r"(a[3]), "r"(b0), "r"(b1));
}
__device__ __forceinline__ void cp16(uint32_t s, const void* g) {
    unsigned long long ga = (unsigned long long)__cvta_generic_to_global(g);
    asm volatile("cp.async.ca.shared.global [%0], [%1], 16;" :: "r"(s), "l"(ga) : "memory");
}
#define CP_COMMIT asm volatile("cp.async.commit_group;" ::: "memory")
#define CP_WAIT0  asm volatile("cp.async.wait_group 0;" ::: "memory")

// ---------------- prep: W fp16 row-major images ----------------
__global__ __launch_bounds__(256) void prep_w(const float* __restrict__ W1,
                                              const float* __restrict__ W2,
                                              const float* __restrict__ W3) {
    int id = blockIdx.x * 256 + threadIdx.x;   // 131072
    const float* W; int base, l;
    if (id < 32768)      { W = W1; base = 0;     l = id; }
    else if (id < 98304) { W = W2; base = 32768; l = id - 32768; }
    else                 { W = W3; base = 98304; l = id - 98304; }
    g_Wh[base + l] = __float2half_rn(W[l]);
}

// ---------------- one layer ----------------
template <int FIN, int FOUT, bool ELU, bool LAST>
__device__ __forceinline__ void layer(char* smem, uint32_t sb, const float* __restrict__ bias,
                                      int wbase, float* __restrict__ outg, int b) {
    const int tid = threadIdx.x, lane = tid & 31, wid = tid >> 5;
    const int wm = wid >> 2, wn = wid & 3;               // 4 x 4 warp grid
    constexpr int NWN = FOUT / 4, NT16 = NWN / 16, NT8 = NWN / 8, KS32 = FIN / 32;

    float* sBias = (float*)(smem + OFF_BIAS);
    const float* sDinv = (const float*)(smem + OFF_DINV);
    const unsigned* sMB = (const unsigned*)(smem + OFF_MB);
    for (int n = tid; n < FOUT; n += 512) sBias[n] = bias[n];

    float acc[2][NT8][4];
#pragma unroll
    for (int m = 0; m < 2; ++m)
#pragma unroll
        for (int i = 0; i < NT8; ++i)
#pragma unroll
            for (int q = 0; q < 4; ++q) acc[m][i][q] = 0.0f;

    // ---- GEMM1: T = H @ W  (single fp16 product), 32-row W blocks ----
    auto stage = [&](int kb, int buf) {
        const int cnt = 32 * FOUT / 8;
        for (int i = tid; i < cnt; i += 512) {
            int r = i / (FOUT / 8), c8 = (i % (FOUT / 8)) * 8;
            size_t go = (size_t)wbase + (size_t)(kb * 32 + r) * FOUT + c8;
            cp16(sb + OFF_W + buf * WBUF + (uint32_t)(r * SW + c8) * 2, g_Wh + go);
        }
    };
    stage(0, 0);
    CP_COMMIT;
    CP_WAIT0;
    __syncthreads();

    const uint32_t aRow  = (uint32_t)(wm * 32 + (lane & 15));
    const uint32_t aCol8 = (uint32_t)((lane >> 4) * 8);
    const uint32_t bRow  = (uint32_t)((lane & 7) + ((lane >> 3) & 1) * 8);
    const uint32_t bCol8 = (uint32_t)((lane >> 4) * 8);

    for (int kb = 0; kb < KS32; ++kb) {
        if (kb + 1 < KS32) stage(kb + 1, (kb + 1) & 1);
        CP_COMMIT;
        uint32_t wb = sb + OFF_W + (kb & 1) * WBUF;
#pragma unroll
        for (int ks = 0; ks < 2; ++ks) {
            const int k = kb * 2 + ks;
            uint32_t ah[2][4];
#pragma unroll
            for (int m = 0; m < 2; ++m) {
                uint32_t aoff = ((aRow + 16 * m) * SH + k * 16 + aCol8) * 2;
                ldsm4(ah[m], sb + OFF_HHI + aoff);
            }
#pragma unroll
            for (int t = 0; t < NT16; ++t) {
                uint32_t boff = ((ks * 16 + bRow) * SW + wn * NWN + t * 16 + bCol8) * 2;
                uint32_t bh[4];
                ldsm4t(bh, wb + boff);
#pragma unroll
                for (int m = 0; m < 2; ++m) {
                    mma16816(acc[m][2 * t], ah[m], bh[0], bh[1]);
                    mma16816(acc[m][2 * t + 1], ah[m], bh[2], bh[3]);
                }
            }
        }
        CP_WAIT0;
        __syncthreads();
    }

    // ---- epilogue1: write T * dinv_row into H buffer ----
#pragma unroll
    for (int m = 0; m < 2; ++m) {
        int r0 = wm * 32 + m * 16 + (lane >> 2), r1 = r0 + 8;
        float d0 = sDinv[r0], d1 = sDinv[r1];
#pragma unroll
        for (int i = 0; i < NT8; ++i) {
            int col = wn * NWN + i * 8 + (lane & 3) * 2;
            *(unsigned*)(smem + OFF_HHI + (r0 * SH + col) * 2) =
                pk(acc[m][i][0] * d0, acc[m][i][1] * d0);
            *(unsigned*)(smem + OFF_HHI + (r1 * SH + col) * 2) =
                pk(acc[m][i][2] * d1, acc[m][i][3] * d1);
        }
    }
    __syncthreads();

    // ---- GEMM2: out = Mask @ T (mask fragments from bitmask registers) ----
    float ac2[2][NT8][4];
#pragma unroll
    for (int m = 0; m < 2; ++m)
#pragma unroll
        for (int i = 0; i < NT8; ++i)
#pragma unroll
            for (int q = 0; q < 4; ++q) ac2[m][i][q] = 0.0f;

    unsigned mw[4][4];   // [m*2+p][kword]
#pragma unroll
    for (int m = 0; m < 2; ++m)
#pragma unroll
        for (int p = 0; p < 2; ++p) {
            int r = wm * 32 + m * 16 + p * 8 + (lane >> 2);
#pragma unroll
            for (int kw = 0; kw < 4; ++kw) mw[m * 2 + p][kw] = sMB[r * 4 + kw];
        }
    const int cbit = (lane & 3) * 2;

    for (int k = 0; k < 8; ++k) {
        uint32_t am[2][4];
#pragma unroll
        for (int m = 0; m < 2; ++m) {
            unsigned f0 = mw[m * 2 + 0][k >> 1] >> ((k & 1) * 16);
            unsigned f1 = mw[m * 2 + 1][k >> 1] >> ((k & 1) * 16);
            am[m][0] = ((f0 >> cbit) & 1u) * 0x3C00u + ((f0 >> (cbit + 1)) & 1u) * 0x3C000000u;
            am[m][1] = ((f1 >> cbit) & 1u) * 0x3C00u + ((f1 >> (cbit + 1)) & 1u) * 0x3C000000u;
            am[m][2] = ((f0 >> (cbit + 8)) & 1u) * 0x3C00u + ((f0 >> (cbit + 9)) & 1u) * 0x3C000000u;
            am[m][3] = ((f1 >> (cbit + 8)) & 1u) * 0x3C00u + ((f1 >> (cbit + 9)) & 1u) * 0x3C000000u;
        }
#pragma unroll
        for (int t = 0; t < NT16; ++t) {
            uint32_t boff = ((k * 16 + bRow) * SH + wn * NWN + t * 16 + bCol8) * 2;
            uint32_t th[4];
            ldsm4t(th, sb + OFF_HHI + boff);
#pragma unroll
            for (int m = 0; m < 2; ++m) {
                mma16816(ac2[m][2 * t], am[m], th[0], th[1]);
                mma16816(ac2[m][2 * t + 1], am[m], th[2], th[3]);
            }
        }
    }
    __syncthreads();

    // ---- epilogue2: *dinv_i + bias, ELU, write next-H or global out ----
#pragma unroll
    for (int m = 0; m < 2; ++m) {
        int r0 = wm * 32 + m * 16 + (lane >> 2), r1 = r0 + 8;
        float d0 = sDinv[r0], d1 = sDinv[r1];
#pragma unroll
        for (int i = 0; i < NT8; ++i) {
            int col = wn * NWN + i * 8 + (lane & 3) * 2;
            float b0v = sBias[col], b1v = sBias[col + 1];
            float v00 = fmaf(ac2[m][i][0], d0, b0v), v01 = fmaf(ac2[m][i][1], d0, b1v);
            float v10 = fmaf(ac2[m][i][2], d1, b0v), v11 = fmaf(ac2[m][i][3], d1, b1v);
            if (ELU) {
                v00 = v00 > 0.f ? v00 : expm1f(v00);
                v01 = v01 > 0.f ? v01 : expm1f(v01);
                v10 = v10 > 0.f ? v10 : expm1f(v10);
                v11 = v11 > 0.f ? v11 : expm1f(v11);
            }
            if (LAST) {
                *(float2*)(outg + ((size_t)b * 128 + r0) * 128 + col) = make_float2(v00, v01);
                *(float2*)(outg + ((size_t)b * 128 + r1) * 128 + col) = make_float2(v10, v11);
            } else {
                *(unsigned*)(smem + OFF_HHI + (r0 * SH + col) * 2) = pk(v00, v01);
                *(unsigned*)(smem + OFF_HHI + (r1 * SH + col) * 2) = pk(v10, v11);
            }
        }
    }
    __syncthreads();
}

// ---------------- fused kernel (mask build fused in) ----------------
__global__ void __launch_bounds__(512, 1) gcn_fused(
    const float* __restrict__ x, const float* __restrict__ adj,
    const float* __restrict__ b1, const float* __restrict__ b2,
    const float* __restrict__ b3, float* __restrict__ out) {
    extern __shared__ char smem[];
    const uint32_t sb = s2u(smem);
    const int b = blockIdx.x, tid = threadIdx.x;
    const int warp = tid >> 5, lane = tid & 31;

    // build 128-bit row masks + dinv from adj (ballot), directly in smem
    unsigned* sMB = (unsigned*)(smem + OFF_MB);
    float* sDinv = (float*)(smem + OFF_DINV);
    const float* ab = adj + (size_t)b * 16384;
    for (int r = warp; r < 128; r += 16) {
        const float* a = ab + r * 128;
        unsigned m[4]; int deg = 0;
#pragma unroll
        for (int s = 0; s < 4; ++s) {
            unsigned w = __ballot_sync(0xffffffffu, a[lane + 32 * s] != 0.0f);
            if (s == (r >> 5)) w |= 1u << (r & 31);
            m[s] = w; deg += __popc(w);
        }
        if (lane == 0) {
            sDinv[r] = rsqrtf((float)deg);
#pragma unroll
            for (int s = 0; s < 4; ++s) sMB[r * 4 + s] = m[s];
        }
    }

    // stage x as fp16
    const float* xb = x + (size_t)b * 16384;
    for (int idx = tid; idx < 8192; idx += 512) {
        int r = idx >> 6, c2 = (idx & 63) * 2;
        *(unsigned*)(smem + OFF_HHI + (r * SH + c2) * 2) =
            pk(xb[r * 128 + c2], xb[r * 128 + c2 + 1]);
    }
    __syncthreads();

    layer<128, 256, true,  false>(smem, sb, b1, 0,     out, b);
    layer<256, 256, true,  false>(smem, sb, b2, 32768, out, b);
    layer<256, 128, false, true >(smem, sb, b3, 98304, out, b);
}

// ---------------------------------------------------------------------------
extern "C" void kernel_launch(void* const* d_in, const int* in_sizes, int n_in,
                              void* d_out, int out_size) {
    const float* x   = (const float*)d_in[0];
    const float* adj = (const float*)d_in[1];
    const float* W1  = (const float*)d_in[2];
    const float* b1  = (const float*)d_in[3];
    const float* W2  = (const float*)d_in[4];
    const float* b2  = (const float*)d_in[5];
    const float* W3  = (const float*)d_in[6];
    const float* b3  = (const float*)d_in[7];
    float* out = (float*)d_out;

    cudaFuncSetAttribute(gcn_fused, cudaFuncAttributeMaxDynamicSharedMemorySize, SMEM_SZ);
    prep_w<<<512, 256>>>(W1, W2, W3);
    gcn_fused<<<NB, 512, SMEM_SZ>>>(x, adj, b1, b2, b3, out);
}

// round 10
// speedup vs baseline: 4.8393x; 1.1707x over previous
#include <cuda_runtime.h>
#include <cuda_fp16.h>
#include <stdint.h>
#include <math.h>

#define NB 1024

__device__ __align__(16) __half g_Wh[131072];  // W1|W2|W3 row-major [FIN][FOUT], fp16

// ---- smem layout (bytes) ----
#define OFF_BIAS 0
#define OFF_DINV 1024
#define OFF_MB   1536        // bitmask [128][4] words
#define OFF_HHI  3584        // H/T fp16 [128][264]
#define OFF_W    71168       // 2 x Whi[64][264]
#define WBUF     33792
#define SMEM_SZ  138752
#define SH 264
#define SW 264

__device__ __forceinline__ uint32_t s2u(const void* p) {
    uint32_t a;
    asm("{ .reg .u64 t; cvta.to.shared.u64 t, %1; cvt.u32.u64 %0, t; }" : "=r"(a) : "l"(p));
    return a;
}
__device__ __forceinline__ unsigned pk(float a, float b) {   // lo=a, hi=b
    __half2 h = __floats2half2_rn(a, b);
    return *(unsigned*)&h;
}
__device__ __forceinline__ float elu_neg(float v) {          // v <= 0 branch
    return __expf(v) - 1.0f;
}
__device__ __forceinline__ void ldsm4(uint32_t* r, uint32_t a) {
    asm volatile("ldmatrix.sync.aligned.m8n8.x4.shared.b16 {%0,%1,%2,%3}, [%4];"
                 : "=r"(r[0]), "=r"(r[1]), "=r"(r[2]), "=r"(r[3]) : "r"(a));
}
__device__ __forceinline__ void ldsm4t(uint32_t* r, uint32_t a) {
    asm volatile("ldmatrix.sync.aligned.m8n8.x4.trans.shared.b16 {%0,%1,%2,%3}, [%4];"
                 : "=r"(r[0]), "=r"(r[1]), "=r"(r[2]), "=r"(r[3]) : "r"(a));
}
__device__ __forceinline__ void mma16816(float* c, const uint32_t* a, uint32_t b0, uint32_t b1) {
    asm volatile(
        "mma.sync.aligned.m16n8k16.row.col.f32.f16.f16.f32 "
        "{%0,%1,%2,%3}, {%4,%5,%6,%7}, {%8,%9}, {%0,%1,%2,%3};"
        : "+f"(c[0]), "+f"(c[1]), "+f"(c[2]), "+f"(c[3])
        : "r"(a[0]), "r"(a[1]), "r"(a[2]), "r"(a[3]), "r"(b0), "r"(b1));
}
__device__ __forceinline__ void cp16(uint32_t s, const void* g) {
    unsigned long long ga = (unsigned long long)__cvta_generic_to_global(g);
    asm volatile("cp.async.ca.shared.global [%0], [%1], 16;" :: "r"(s), "l"(ga) : "memory");
}
#define CP_COMMIT asm volatile("cp.async.commit_group;" ::: "memory")
#define CP_WAIT0  asm volatile("cp.async.wait_group 0;" ::: "memory")

// ---------------- prep: W fp16 row-major images ----------------
__global__ __launch_bounds__(256) void prep_w(const float* __restrict__ W1,
                                              const float* __restrict__ W2,
                                              const float* __restrict__ W3) {
    int id = blockIdx.x * 256 + threadIdx.x;   // 131072
    const float* W; int base, l;
    if (id < 32768)      { W = W1; base = 0;     l = id; }
    else if (id < 98304) { W = W2; base = 32768; l = id - 32768; }
    else                 { W = W3; base = 98304; l = id - 98304; }
    g_Wh[base + l] = __float2half_rn(W[l]);
}

// ---------------- one layer ----------------
template <int FIN, int FOUT, bool ELU, bool LAST>
__device__ __forceinline__ void layer(char* smem, uint32_t sb, const float* __restrict__ bias,
                                      int wbase, float* __restrict__ outg, int b) {
    const int tid = threadIdx.x, lane = tid & 31, wid = tid >> 5;
    const int wm = wid >> 2, wn = wid & 3;               // 4 x 4 warp grid
    constexpr int NWN = FOUT / 4, NT16 = NWN / 16, NT8 = NWN / 8, KB = FIN / 64;

    float* sBias = (float*)(smem + OFF_BIAS);
    const float* sDinv = (const float*)(smem + OFF_DINV);
    const unsigned* sMB = (const unsigned*)(smem + OFF_MB);
    for (int n = tid; n < FOUT; n += 512) sBias[n] = bias[n];

    float acc[2][NT8][4];
#pragma unroll
    for (int m = 0; m < 2; ++m)
#pragma unroll
        for (int i = 0; i < NT8; ++i)
#pragma unroll
            for (int q = 0; q < 4; ++q) acc[m][i][q] = 0.0f;

    // ---- GEMM1: T = H @ W  (single fp16 product), 64-row W blocks ----
    auto stage = [&](int kb, int buf) {
        const int cnt = 64 * FOUT / 8;
        for (int i = tid; i < cnt; i += 512) {
            int r = i / (FOUT / 8), c8 = (i % (FOUT / 8)) * 8;
            size_t go = (size_t)wbase + (size_t)(kb * 64 + r) * FOUT + c8;
            cp16(sb + OFF_W + buf * WBUF + (uint32_t)(r * SW + c8) * 2, g_Wh + go);
        }
    };
    stage(0, 0);
    CP_COMMIT;
    CP_WAIT0;
    __syncthreads();

    const uint32_t aRow  = (uint32_t)(wm * 32 + (lane & 15));
    const uint32_t aCol8 = (uint32_t)((lane >> 4) * 8);
    const uint32_t bRow  = (uint32_t)((lane & 7) + ((lane >> 3) & 1) * 8);
    const uint32_t bCol8 = (uint32_t)((lane >> 4) * 8);

    for (int kb = 0; kb < KB; ++kb) {
        if (kb + 1 < KB) stage(kb + 1, (kb + 1) & 1);
        CP_COMMIT;
        uint32_t wb = sb + OFF_W + (kb & 1) * WBUF;
#pragma unroll
        for (int kh = 0; kh < 2; ++kh) {
            uint32_t ah[2][2][4];                        // [kstep-pair][m][frag]
#pragma unroll
            for (int ks = 0; ks < 2; ++ks) {
                const int k = kb * 4 + kh * 2 + ks;
#pragma unroll
                for (int m = 0; m < 2; ++m)
                    ldsm4(ah[ks][m], sb + OFF_HHI + ((aRow + 16 * m) * SH + k * 16 + aCol8) * 2);
            }
#pragma unroll
            for (int ks = 0; ks < 2; ++ks) {
                const int kl = kh * 2 + ks;              // 0..3 within block
#pragma unroll
                for (int t = 0; t < NT16; ++t) {
                    uint32_t boff = ((kl * 16 + bRow) * SW + wn * NWN + t * 16 + bCol8) * 2;
                    uint32_t bh[4];
                    ldsm4t(bh, wb + boff);
#pragma unroll
                    for (int m = 0; m < 2; ++m) {
                        mma16816(acc[m][2 * t], ah[ks][m], bh[0], bh[1]);
                        mma16816(acc[m][2 * t + 1], ah[ks][m], bh[2], bh[3]);
                    }
                }
            }
        }
        CP_WAIT0;
        __syncthreads();
    }

    // ---- epilogue1: write T * dinv_row into H buffer ----
#pragma unroll
    for (int m = 0; m < 2; ++m) {
        int r0 = wm * 32 + m * 16 + (lane >> 2), r1 = r0 + 8;
        float d0 = sDinv[r0], d1 = sDinv[r1];
#pragma unroll
        for (int i = 0; i < NT8; ++i) {
            int col = wn * NWN + i * 8 + (lane & 3) * 2;
            *(unsigned*)(smem + OFF_HHI + (r0 * SH + col) * 2) =
                pk(acc[m][i][0] * d0, acc[m][i][1] * d0);
            *(unsigned*)(smem + OFF_HHI + (r1 * SH + col) * 2) =
                pk(acc[m][i][2] * d1, acc[m][i][3] * d1);
        }
    }
    __syncthreads();

    // ---- GEMM2: out = Mask @ T (mask fragments from bitmask registers) ----
    float ac2[2][NT8][4];
#pragma unroll
    for (int m = 0; m < 2; ++m)
#pragma unroll
        for (int i = 0; i < NT8; ++i)
#pragma unroll
            for (int q = 0; q < 4; ++q) ac2[m][i][q] = 0.0f;

    unsigned mw[4][4];   // [m*2+p][kword]
#pragma unroll
    for (int m = 0; m < 2; ++m)
#pragma unroll
        for (int p = 0; p < 2; ++p) {
            int r = wm * 32 + m * 16 + p * 8 + (lane >> 2);
#pragma unroll
            for (int kw = 0; kw < 4; ++kw) mw[m * 2 + p][kw] = sMB[r * 4 + kw];
        }
    const int cbit = (lane & 3) * 2;

    for (int k = 0; k < 8; ++k) {
        uint32_t am[2][4];
#pragma unroll
        for (int m = 0; m < 2; ++m) {
            unsigned f0 = mw[m * 2 + 0][k >> 1] >> ((k & 1) * 16);
            unsigned f1 = mw[m * 2 + 1][k >> 1] >> ((k & 1) * 16);
            am[m][0] = ((f0 >> cbit) & 1u) * 0x3C00u + ((f0 >> (cbit + 1)) & 1u) * 0x3C000000u;
            am[m][1] = ((f1 >> cbit) & 1u) * 0x3C00u + ((f1 >> (cbit + 1)) & 1u) * 0x3C000000u;
            am[m][2] = ((f0 >> (cbit + 8)) & 1u) * 0x3C00u + ((f0 >> (cbit + 9)) & 1u) * 0x3C000000u;
            am[m][3] = ((f1 >> (cbit + 8)) & 1u) * 0x3C00u + ((f1 >> (cbit + 9)) & 1u) * 0x3C000000u;
        }
#pragma unroll
        for (int t = 0; t < NT16; ++t) {
            uint32_t boff = ((k * 16 + bRow) * SH + wn * NWN + t * 16 + bCol8) * 2;
            uint32_t th[4];
            ldsm4t(th, sb + OFF_HHI + boff);
#pragma unroll
            for (int m = 0; m < 2; ++m) {
                mma16816(ac2[m][2 * t], am[m], th[0], th[1]);
                mma16816(ac2[m][2 * t + 1], am[m], th[2], th[3]);
            }
        }
    }
    __syncthreads();

    // ---- epilogue2: *dinv_i + bias, ELU, write next-H or global out ----
#pragma unroll
    for (int m = 0; m < 2; ++m) {
        int r0 = wm * 32 + m * 16 + (lane >> 2), r1 = r0 + 8;
        float d0 = sDinv[r0], d1 = sDinv[r1];
#pragma unroll
        for (int i = 0; i < NT8; ++i) {
            int col = wn * NWN + i * 8 + (lane & 3) * 2;
            float b0v = sBias[col], b1v = sBias[col + 1];
            float v00 = fmaf(ac2[m][i][0], d0, b0v), v01 = fmaf(ac2[m][i][1], d0, b1v);
            float v10 = fmaf(ac2[m][i][2], d1, b0v), v11 = fmaf(ac2[m][i][3], d1, b1v);
            if (ELU) {
                v00 = v00 > 0.f ? v00 : elu_neg(v00);
                v01 = v01 > 0.f ? v01 : elu_neg(v01);
                v10 = v10 > 0.f ? v10 : elu_neg(v10);
                v11 = v11 > 0.f ? v11 : elu_neg(v11);
            }
            if (LAST) {
                *(float2*)(outg + ((size_t)b * 128 + r0) * 128 + col) = make_float2(v00, v01);
                *(float2*)(outg + ((size_t)b * 128 + r1) * 128 + col) = make_float2(v10, v11);
            } else {
                *(unsigned*)(smem + OFF_HHI + (r0 * SH + col) * 2) = pk(v00, v01);
                *(unsigned*)(smem + OFF_HHI + (r1 * SH + col) * 2) = pk(v10, v11);
            }
        }
    }
    __syncthreads();
}

// ---------------- fused kernel (mask build fused in) ----------------
__global__ void __launch_bounds__(512, 1) gcn_fused(
    const float* __restrict__ x, const float* __restrict__ adj,
    const float* __restrict__ b1, const float* __restrict__ b2,
    const float* __restrict__ b3, float* __restrict__ out) {
    extern __shared__ char smem[];
    const uint32_t sb = s2u(smem);
    const int b = blockIdx.x, tid = threadIdx.x;
    const int warp = tid >> 5, lane = tid & 31;

    // build 128-bit row masks + dinv from adj (ballot), directly in smem
    unsigned* sMB = (unsigned*)(smem + OFF_MB);
    float* sDinv = (float*)(smem + OFF_DINV);
    const float* ab = adj + (size_t)b * 16384;
    for (int r = warp; r < 128; r += 16) {
        const float* a = ab + r * 128;
        unsigned m[4]; int deg = 0;
#pragma unroll
        for (int s = 0; s < 4; ++s) {
            unsigned w = __ballot_sync(0xffffffffu, a[lane + 32 * s] != 0.0f);
            if (s == (r >> 5)) w |= 1u << (r & 31);
            m[s] = w; deg += __popc(w);
        }
        if (lane == 0) {
            sDinv[r] = rsqrtf((float)deg);
#pragma unroll
            for (int s = 0; s < 4; ++s) sMB[r * 4 + s] = m[s];
        }
    }

    // stage x as fp16
    const float* xb = x + (size_t)b * 16384;
    for (int idx = tid; idx < 8192; idx += 512) {
        int r = idx >> 6, c2 = (idx & 63) * 2;
        *(unsigned*)(smem + OFF_HHI + (r * SH + c2) * 2) =
            pk(xb[r * 128 + c2], xb[r * 128 + c2 + 1]);
    }
    __syncthreads();

    layer<128, 256, true,  false>(smem, sb, b1, 0,     out, b);
    layer<256, 256, true,  false>(smem, sb, b2, 32768, out, b);
    layer<256, 128, false, true >(smem, sb, b3, 98304, out, b);
}

// ---------------------------------------------------------------------------
extern "C" void kernel_launch(void* const* d_in, const int* in_sizes, int n_in,
                              void* d_out, int out_size) {
    const float* x   = (const float*)d_in[0];
    const float* adj = (const float*)d_in[1];
    const float* W1  = (const float*)d_in[2];
    const float* b1  = (const float*)d_in[3];
    const float* W2  = (const float*)d_in[4];
    const float* b2  = (const float*)d_in[5];
    const float* W3  = (const float*)d_in[6];
    const float* b3  = (const float*)d_in[7];
    float* out = (float*)d_out;

    cudaFuncSetAttribute(gcn_fused, cudaFuncAttributeMaxDynamicSharedMemorySize, SMEM_SZ);
    prep_w<<<512, 256>>>(W1, W2, W3);
    gcn_fused<<<NB, 512, SMEM_SZ>>>(x, adj, b1, b2, b3, out);
}

// round 11
// speedup vs baseline: 5.6578x; 1.1691x over previous
#include <cuda_runtime.h>
#include <cuda_fp16.h>
#include <stdint.h>
#include <math.h>

#define NB 1024

__device__ __align__(16) __half g_Wh[131072];  // W1|W2|W3 row-major [FIN][FOUT], fp16

// ---- smem layout (bytes) ----
#define OFF_BIAS 0
#define OFF_DINV 1024
#define OFF_MSK  3584        // mask fp16 [128][136] (built once, layer-invariant)
#define OFF_HHI  38400       // H/T fp16 [128][264]
#define OFF_W    105984      // 2 x Whi[64][264]
#define WBUF     33792
#define SMEM_SZ  173568
#define SH 264
#define SM 136
#define SW 264

__device__ __forceinline__ uint32_t s2u(const void* p) {
    uint32_t a;
    asm("{ .reg .u64 t; cvta.to.shared.u64 t, %1; cvt.u32.u64 %0, t; }" : "=r"(a) : "l"(p));
    return a;
}
__device__ __forceinline__ unsigned pk(float a, float b) {   // lo=a, hi=b
    __half2 h = __floats2half2_rn(a, b);
    return *(unsigned*)&h;
}
__device__ __forceinline__ float elu_neg(float v) {          // v <= 0 branch
    return __expf(v) - 1.0f;
}
__device__ __forceinline__ void ldsm4(uint32_t* r, uint32_t a) {
    asm volatile("ldmatrix.sync.aligned.m8n8.x4.shared.b16 {%0,%1,%2,%3}, [%4];"
                 : "=r"(r[0]), "=r"(r[1]), "=r"(r[2]), "=r"(r[3]) : "r"(a));
}
__device__ __forceinline__ void ldsm4t(uint32_t* r, uint32_t a) {
    asm volatile("ldmatrix.sync.aligned.m8n8.x4.trans.shared.b16 {%0,%1,%2,%3}, [%4];"
                 : "=r"(r[0]), "=r"(r[1]), "=r"(r[2]), "=r"(r[3]) : "r"(a));
}
__device__ __forceinline__ void mma16816(float* c, const uint32_t* a, uint32_t b0, uint32_t b1) {
    asm volatile(
        "mma.sync.aligned.m16n8k16.row.col.f32.f16.f16.f32 "
        "{%0,%1,%2,%3}, {%4,%5,%6,%7}, {%8,%9}, {%0,%1,%2,%3};"
        : "+f"(c[0]), "+f"(c[1]), "+f"(c[2]), "+f"(c[3])
        : "r"(a[0]), "r"(a[1]), "r"(a[2]), "r"(a[3]), "r"(b0), "r"(b1));
}
__device__ __forceinline__ void cp16(uint32_t s, const void* g) {
    unsigned long long ga = (unsigned long long)__cvta_generic_to_global(g);
    asm volatile("cp.async.ca.shared.global [%0], [%1], 16;" :: "r"(s), "l"(ga) : "memory");
}
#define CP_COMMIT asm volatile("cp.async.commit_group;" ::: "memory")
#define CP_WAIT0  asm volatile("cp.async.wait_group 0;" ::: "memory")

// ---------------- prep: W fp16 row-major images ----------------
__global__ __launch_bounds__(256) void prep_w(const float* __restrict__ W1,
                                              const float* __restrict__ W2,
                                              const float* __restrict__ W3) {
    int id = blockIdx.x * 256 + threadIdx.x;   // 131072
    const float* W; int base, l;
    if (id < 32768)      { W = W1; base = 0;     l = id; }
    else if (id < 98304) { W = W2; base = 32768; l = id - 32768; }
    else                 { W = W3; base = 98304; l = id - 98304; }
    g_Wh[base + l] = __float2half_rn(W[l]);
}

// ---------------- one layer ----------------
template <int FIN, int FOUT, bool ELU, bool LAST>
__device__ __forceinline__ void layer(char* smem, uint32_t sb, const float* __restrict__ bias,
                                      int wbase, float* __restrict__ outg, int b) {
    const int tid = threadIdx.x, lane = tid & 31, wid = tid >> 5;
    const int wm = wid >> 2, wn = wid & 3;               // 4 x 4 warp grid
    constexpr int NWN = FOUT / 4, NT16 = NWN / 16, NT8 = NWN / 8, KB = FIN / 64;

    float* sBias = (float*)(smem + OFF_BIAS);
    const float* sDinv = (const float*)(smem + OFF_DINV);
    for (int n = tid; n < FOUT; n += 512) sBias[n] = bias[n];

    float acc[2][NT8][4];
#pragma unroll
    for (int m = 0; m < 2; ++m)
#pragma unroll
        for (int i = 0; i < NT8; ++i)
#pragma unroll
            for (int q = 0; q < 4; ++q) acc[m][i][q] = 0.0f;

    // ---- GEMM1: T = H @ W  (single fp16 product), 64-row W blocks ----
    auto stage = [&](int kb, int buf) {
        const int cnt = 64 * FOUT / 8;
        for (int i = tid; i < cnt; i += 512) {
            int r = i / (FOUT / 8), c8 = (i % (FOUT / 8)) * 8;
            size_t go = (size_t)wbase + (size_t)(kb * 64 + r) * FOUT + c8;
            cp16(sb + OFF_W + buf * WBUF + (uint32_t)(r * SW + c8) * 2, g_Wh + go);
        }
    };
    stage(0, 0);
    CP_COMMIT;
    CP_WAIT0;
    __syncthreads();

    const uint32_t aRow  = (uint32_t)(wm * 32 + (lane & 15));
    const uint32_t aCol8 = (uint32_t)((lane >> 4) * 8);
    const uint32_t bRow  = (uint32_t)((lane & 7) + ((lane >> 3) & 1) * 8);
    const uint32_t bCol8 = (uint32_t)((lane >> 4) * 8);

    for (int kb = 0; kb < KB; ++kb) {
        if (kb + 1 < KB) stage(kb + 1, (kb + 1) & 1);
        CP_COMMIT;
        uint32_t wb = sb + OFF_W + (kb & 1) * WBUF;
#pragma unroll
        for (int kh = 0; kh < 2; ++kh) {
            uint32_t ah[2][2][4];                        // [kstep-pair][m][frag]
#pragma unroll
            for (int ks = 0; ks < 2; ++ks) {
                const int k = kb * 4 + kh * 2 + ks;
#pragma unroll
                for (int m = 0; m < 2; ++m)
                    ldsm4(ah[ks][m], sb + OFF_HHI + ((aRow + 16 * m) * SH + k * 16 + aCol8) * 2);
            }
#pragma unroll
            for (int ks = 0; ks < 2; ++ks) {
                const int kl = kh * 2 + ks;              // 0..3 within block
#pragma unroll
                for (int t = 0; t < NT16; ++t) {
                    uint32_t boff = ((kl * 16 + bRow) * SW + wn * NWN + t * 16 + bCol8) * 2;
                    uint32_t bh[4];
                    ldsm4t(bh, wb + boff);
#pragma unroll
                    for (int m = 0; m < 2; ++m) {
                        mma16816(acc[m][2 * t], ah[ks][m], bh[0], bh[1]);
                        mma16816(acc[m][2 * t + 1], ah[ks][m], bh[2], bh[3]);
                    }
                }
            }
        }
        CP_WAIT0;
        __syncthreads();
    }

    // ---- epilogue1: write T * dinv_row into H buffer ----
#pragma unroll
    for (int m = 0; m < 2; ++m) {
        int r0 = wm * 32 + m * 16 + (lane >> 2), r1 = r0 + 8;
        float d0 = sDinv[r0], d1 = sDinv[r1];
#pragma unroll
        for (int i = 0; i < NT8; ++i) {
            int col = wn * NWN + i * 8 + (lane & 3) * 2;
            *(unsigned*)(smem + OFF_HHI + (r0 * SH + col) * 2) =
                pk(acc[m][i][0] * d0, acc[m][i][1] * d0);
            *(unsigned*)(smem + OFF_HHI + (r1 * SH + col) * 2) =
                pk(acc[m][i][2] * d1, acc[m][i][3] * d1);
        }
    }
    __syncthreads();

    // ---- GEMM2: out = Mask @ T (mask A-fragments via ldmatrix from smem) ----
    float ac2[2][NT8][4];
#pragma unroll
    for (int m = 0; m < 2; ++m)
#pragma unroll
        for (int i = 0; i < NT8; ++i)
#pragma unroll
            for (int q = 0; q < 4; ++q) ac2[m][i][q] = 0.0f;

    for (int k = 0; k < 8; ++k) {
        uint32_t am[2][4];
#pragma unroll
        for (int m = 0; m < 2; ++m)
            ldsm4(am[m], sb + OFF_MSK + ((aRow + 16 * m) * SM + k * 16 + aCol8) * 2);
#pragma unroll
        for (int t = 0; t < NT16; ++t) {
            uint32_t boff = ((k * 16 + bRow) * SH + wn * NWN + t * 16 + bCol8) * 2;
            uint32_t th[4];
            ldsm4t(th, sb + OFF_HHI + boff);
#pragma unroll
            for (int m = 0; m < 2; ++m) {
                mma16816(ac2[m][2 * t], am[m], th[0], th[1]);
                mma16816(ac2[m][2 * t + 1], am[m], th[2], th[3]);
            }
        }
    }
    __syncthreads();

    // ---- epilogue2: *dinv_i + bias, ELU, write next-H or global out ----
#pragma unroll
    for (int m = 0; m < 2; ++m) {
        int r0 = wm * 32 + m * 16 + (lane >> 2), r1 = r0 + 8;
        float d0 = sDinv[r0], d1 = sDinv[r1];
#pragma unroll
        for (int i = 0; i < NT8; ++i) {
            int col = wn * NWN + i * 8 + (lane & 3) * 2;
            float b0v = sBias[col], b1v = sBias[col + 1];
            float v00 = fmaf(ac2[m][i][0], d0, b0v), v01 = fmaf(ac2[m][i][1], d0, b1v);
            float v10 = fmaf(ac2[m][i][2], d1, b0v), v11 = fmaf(ac2[m][i][3], d1, b1v);
            if (ELU) {
                v00 = v00 > 0.f ? v00 : elu_neg(v00);
                v01 = v01 > 0.f ? v01 : elu_neg(v01);
                v10 = v10 > 0.f ? v10 : elu_neg(v10);
                v11 = v11 > 0.f ? v11 : elu_neg(v11);
            }
            if (LAST) {
                *(float2*)(outg + ((size_t)b * 128 + r0) * 128 + col) = make_float2(v00, v01);
                *(float2*)(outg + ((size_t)b * 128 + r1) * 128 + col) = make_float2(v10, v11);
            } else {
                *(unsigned*)(smem + OFF_HHI + (r0 * SH + col) * 2) = pk(v00, v01);
                *(unsigned*)(smem + OFF_HHI + (r1 * SH + col) * 2) = pk(v10, v11);
            }
        }
    }
    __syncthreads();
}

// ---------------- fused kernel ----------------
__global__ void __launch_bounds__(512, 1) gcn_fused(
    const float* __restrict__ x, const float* __restrict__ adj,
    const float* __restrict__ b1, const float* __restrict__ b2,
    const float* __restrict__ b3, float* __restrict__ out) {
    extern __shared__ char smem[];
    const uint32_t sb = s2u(smem);
    const int b = blockIdx.x, tid = threadIdx.x;
    const int warp = tid >> 5, lane = tid & 31;

    // build dinv + fp16 mask matrix (layer-invariant) straight from ballots
    float* sDinv = (float*)(smem + OFF_DINV);
    const float* ab = adj + (size_t)b * 16384;
    for (int r = warp; r < 128; r += 16) {
        const float* a = ab + r * 128;
        unsigned m[4]; int deg = 0;
#pragma unroll
        for (int s = 0; s < 4; ++s) {
            unsigned w = __ballot_sync(0xffffffffu, a[lane + 32 * s] != 0.0f);
            if (s == (r >> 5)) w |= 1u << (r & 31);
            m[s] = w; deg += __popc(w);
        }
        if (lane == 0) sDinv[r] = rsqrtf((float)deg);
        // each lane writes mask cols 4*lane .. 4*lane+3 of row r
        unsigned w = m[lane >> 3];
        int s4 = (lane & 7) * 4;
        unsigned u0 = (((w >> s4) & 1u) ? 0x3C00u : 0u) | (((w >> (s4 + 1)) & 1u) ? 0x3C000000u : 0u);
        unsigned u1 = (((w >> (s4 + 2)) & 1u) ? 0x3C00u : 0u) | (((w >> (s4 + 3)) & 1u) ? 0x3C000000u : 0u);
        *(uint2*)(smem + OFF_MSK + (r * SM + lane * 4) * 2) = make_uint2(u0, u1);
    }

    // stage x as fp16
    const float* xb = x + (size_t)b * 16384;
    for (int idx = tid; idx < 8192; idx += 512) {
        int r = idx >> 6, c2 = (idx & 63) * 2;
        *(unsigned*)(smem + OFF_HHI + (r * SH + c2) * 2) =
            pk(xb[r * 128 + c2], xb[r * 128 + c2 + 1]);
    }
    __syncthreads();

    layer<128, 256, true,  false>(smem, sb, b1, 0,     out, b);
    layer<256, 256, true,  false>(smem, sb, b2, 32768, out, b);
    layer<256, 128, false, true >(smem, sb, b3, 98304, out, b);
}

// ---------------------------------------------------------------------------
extern "C" void kernel_launch(void* const* d_in, const int* in_sizes, int n_in,
                              void* d_out, int out_size) {
    const float* x   = (const float*)d_in[0];
    const float* adj = (const float*)d_in[1];
    const float* W1  = (const float*)d_in[2];
    const float* b1  = (const float*)d_in[3];
    const float* W2  = (const float*)d_in[4];
    const float* b2  = (const float*)d_in[5];
    const float* W3  = (const float*)d_in[6];
    const float* b3  = (const float*)d_in[7];
    float* out = (float*)d_out;

    cudaFuncSetAttribute(gcn_fused, cudaFuncAttributeMaxDynamicSharedMemorySize, SMEM_SZ);
    prep_w<<<512, 256>>>(W1, W2, W3);
    gcn_fused<<<NB, 512, SMEM_SZ>>>(x, adj, b1, b2, b3, out);
}

// round 12
// speedup vs baseline: 5.7123x; 1.0096x over previous
#include <cuda_runtime.h>
#include <cuda_fp16.h>
#include <stdint.h>
#include <math.h>

#define NB 1024

__device__ __align__(16) __half g_Wh[131072];  // W1|W2|W3 row-major [FIN][FOUT], fp16

// ---- smem layout (bytes) ----
#define OFF_BIAS 0
#define OFF_DINV 1024
#define OFF_MSK  3584        // mask fp16 [128][136] (built once, layer-invariant)
#define OFF_HHI  38400       // H/T fp16 [128][264]
#define OFF_W    105984      // 2 x Whi[64][264]
#define WBUF     33792
#define SMEM_SZ  173568
#define SH 264
#define SM 136
#define SW 264

__device__ __forceinline__ uint32_t s2u(const void* p) {
    uint32_t a;
    asm("{ .reg .u64 t; cvta.to.shared.u64 t, %1; cvt.u32.u64 %0, t; }" : "=r"(a) : "l"(p));
    return a;
}
__device__ __forceinline__ unsigned pk(float a, float b) {   // lo=a, hi=b
    __half2 h = __floats2half2_rn(a, b);
    return *(unsigned*)&h;
}
__device__ __forceinline__ float elu_neg(float v) {          // v <= 0 branch
    return __expf(v) - 1.0f;
}
__device__ __forceinline__ void ldsm4(uint32_t* r, uint32_t a) {
    asm volatile("ldmatrix.sync.aligned.m8n8.x4.shared.b16 {%0,%1,%2,%3}, [%4];"
                 : "=r"(r[0]), "=r"(r[1]), "=r"(r[2]), "=r"(r[3]) : "r"(a));
}
__device__ __forceinline__ void ldsm4t(uint32_t* r, uint32_t a) {
    asm volatile("ldmatrix.sync.aligned.m8n8.x4.trans.shared.b16 {%0,%1,%2,%3}, [%4];"
                 : "=r"(r[0]), "=r"(r[1]), "=r"(r[2]), "=r"(r[3]) : "r"(a));
}
__device__ __forceinline__ void mma16816(float* c, const uint32_t* a, uint32_t b0, uint32_t b1) {
    asm volatile(
        "mma.sync.aligned.m16n8k16.row.col.f32.f16.f16.f32 "
        "{%0,%1,%2,%3}, {%4,%5,%6,%7}, {%8,%9}, {%0,%1,%2,%3};"
        : "+f"(c[0]), "+f"(c[1]), "+f"(c[2]), "+f"(c[3])
        : "r"(a[0]), "r"(a[1]), "r"(a[2]), "r"(a[3]), "r"(b0), "r"(b1));
}
__device__ __forceinline__ void cp16(uint32_t s, const void* g) {
    unsigned long long ga = (unsigned long long)__cvta_generic_to_global(g);
    asm volatile("cp.async.ca.shared.global [%0], [%1], 16;" :: "r"(s), "l"(ga) : "memory");
}
#define CP_COMMIT asm volatile("cp.async.commit_group;" ::: "memory")
#define CP_WAIT0  asm volatile("cp.async.wait_group 0;" ::: "memory")

// ---------------- prep: W fp16 row-major images ----------------
__global__ __launch_bounds__(256) void prep_w(const float* __restrict__ W1,
                                              const float* __restrict__ W2,
                                              const float* __restrict__ W3) {
    int id = blockIdx.x * 256 + threadIdx.x;   // 131072
    const float* W; int base, l;
    if (id < 32768)      { W = W1; base = 0;     l = id; }
    else if (id < 98304) { W = W2; base = 32768; l = id - 32768; }
    else                 { W = W3; base = 98304; l = id - 98304; }
    g_Wh[base + l] = __float2half_rn(W[l]);
}

// ---------------- one layer ----------------
template <int FIN, int FOUT, bool ELU, bool LAST>
__device__ __forceinline__ void layer(char* smem, uint32_t sb, const float* __restrict__ bias,
                                      int wbase, float* __restrict__ outg, int b) {
    const int tid = threadIdx.x, lane = tid & 31, wid = tid >> 5;
    const int wm = wid >> 2, wn = wid & 3;               // 4 x 4 warp grid
    constexpr int NWN = FOUT / 4, NT16 = NWN / 16, NT8 = NWN / 8, KB = FIN / 64;

    float* sBias = (float*)(smem + OFF_BIAS);
    const float* sDinv = (const float*)(smem + OFF_DINV);
    for (int n = tid; n < FOUT; n += 512) sBias[n] = bias[n];

    float acc[2][NT8][4];
#pragma unroll
    for (int m = 0; m < 2; ++m)
#pragma unroll
        for (int i = 0; i < NT8; ++i)
#pragma unroll
            for (int q = 0; q < 4; ++q) acc[m][i][q] = 0.0f;

    // ---- GEMM1: T = H @ W  (single fp16 product), 64-row W blocks ----
    auto stage = [&](int kb, int buf) {
        const int cnt = 64 * FOUT / 8;
        for (int i = tid; i < cnt; i += 512) {
            int r = i / (FOUT / 8), c8 = (i % (FOUT / 8)) * 8;
            size_t go = (size_t)wbase + (size_t)(kb * 64 + r) * FOUT + c8;
            cp16(sb + OFF_W + buf * WBUF + (uint32_t)(r * SW + c8) * 2, g_Wh + go);
        }
    };
    stage(0, 0);
    CP_COMMIT;
    CP_WAIT0;
    __syncthreads();

    const uint32_t aRow  = (uint32_t)(wm * 32 + (lane & 15));
    const uint32_t aCol8 = (uint32_t)((lane >> 4) * 8);
    const uint32_t bRow  = (uint32_t)((lane & 7) + ((lane >> 3) & 1) * 8);
    const uint32_t bCol8 = (uint32_t)((lane >> 4) * 8);

    for (int kb = 0; kb < KB; ++kb) {
        if (kb + 1 < KB) stage(kb + 1, (kb + 1) & 1);
        CP_COMMIT;
        uint32_t wb = sb + OFF_W + (kb & 1) * WBUF;
#pragma unroll
        for (int ks = 0; ks < 4; ++ks) {
            const int k = kb * 4 + ks;
            // batch ALL fragment loads for this k-step, then run the MMA chain
            uint32_t ah[2][4];
#pragma unroll
            for (int m = 0; m < 2; ++m)
                ldsm4(ah[m], sb + OFF_HHI + ((aRow + 16 * m) * SH + k * 16 + aCol8) * 2);
            uint32_t bh[NT16][4];
#pragma unroll
            for (int t = 0; t < NT16; ++t)
                ldsm4t(bh[t], wb + ((ks * 16 + bRow) * SW + wn * NWN + t * 16 + bCol8) * 2);
#pragma unroll
            for (int t = 0; t < NT16; ++t)
#pragma unroll
                for (int m = 0; m < 2; ++m) {
                    mma16816(acc[m][2 * t], ah[m], bh[t][0], bh[t][1]);
                    mma16816(acc[m][2 * t + 1], ah[m], bh[t][2], bh[t][3]);
                }
        }
        CP_WAIT0;
        __syncthreads();
    }

    // ---- epilogue1: write T * dinv_row into H buffer ----
#pragma unroll
    for (int m = 0; m < 2; ++m) {
        int r0 = wm * 32 + m * 16 + (lane >> 2), r1 = r0 + 8;
        float d0 = sDinv[r0], d1 = sDinv[r1];
#pragma unroll
        for (int i = 0; i < NT8; ++i) {
            int col = wn * NWN + i * 8 + (lane & 3) * 2;
            *(unsigned*)(smem + OFF_HHI + (r0 * SH + col) * 2) =
                pk(acc[m][i][0] * d0, acc[m][i][1] * d0);
            *(unsigned*)(smem + OFF_HHI + (r1 * SH + col) * 2) =
                pk(acc[m][i][2] * d1, acc[m][i][3] * d1);
        }
    }
    __syncthreads();

    // ---- GEMM2: out = Mask @ T (batched fragment loads, unrolled k) ----
    float ac2[2][NT8][4];
#pragma unroll
    for (int m = 0; m < 2; ++m)
#pragma unroll
        for (int i = 0; i < NT8; ++i)
#pragma unroll
            for (int q = 0; q < 4; ++q) ac2[m][i][q] = 0.0f;

#pragma unroll
    for (int k = 0; k < 8; ++k) {
        uint32_t am[2][4];
#pragma unroll
        for (int m = 0; m < 2; ++m)
            ldsm4(am[m], sb + OFF_MSK + ((aRow + 16 * m) * SM + k * 16 + aCol8) * 2);
        uint32_t th[NT16][4];
#pragma unroll
        for (int t = 0; t < NT16; ++t)
            ldsm4t(th[t], sb + OFF_HHI + ((k * 16 + bRow) * SH + wn * NWN + t * 16 + bCol8) * 2);
#pragma unroll
        for (int t = 0; t < NT16; ++t)
#pragma unroll
            for (int m = 0; m < 2; ++m) {
                mma16816(ac2[m][2 * t], am[m], th[t][0], th[t][1]);
                mma16816(ac2[m][2 * t + 1], am[m], th[t][2], th[t][3]);
            }
    }
    __syncthreads();

    // ---- epilogue2: *dinv_i + bias, ELU, write next-H or global out ----
#pragma unroll
    for (int m = 0; m < 2; ++m) {
        int r0 = wm * 32 + m * 16 + (lane >> 2), r1 = r0 + 8;
        float d0 = sDinv[r0], d1 = sDinv[r1];
#pragma unroll
        for (int i = 0; i < NT8; ++i) {
            int col = wn * NWN + i * 8 + (lane & 3) * 2;
            float b0v = sBias[col], b1v = sBias[col + 1];
            float v00 = fmaf(ac2[m][i][0], d0, b0v), v01 = fmaf(ac2[m][i][1], d0, b1v);
            float v10 = fmaf(ac2[m][i][2], d1, b0v), v11 = fmaf(ac2[m][i][3], d1, b1v);
            if (ELU) {
                v00 = v00 > 0.f ? v00 : elu_neg(v00);
                v01 = v01 > 0.f ? v01 : elu_neg(v01);
                v10 = v10 > 0.f ? v10 : elu_neg(v10);
                v11 = v11 > 0.f ? v11 : elu_neg(v11);
            }
            if (LAST) {
                *(float2*)(outg + ((size_t)b * 128 + r0) * 128 + col) = make_float2(v00, v01);
                *(float2*)(outg + ((size_t)b * 128 + r1) * 128 + col) = make_float2(v10, v11);
            } else {
                *(unsigned*)(smem + OFF_HHI + (r0 * SH + col) * 2) = pk(v00, v01);
                *(unsigned*)(smem + OFF_HHI + (r1 * SH + col) * 2) = pk(v10, v11);
            }
        }
    }
    __syncthreads();
}

// ---------------- fused kernel ----------------
__global__ void __launch_bounds__(512, 1) gcn_fused(
    const float* __restrict__ x, const float* __restrict__ adj,
    const float* __restrict__ b1, const float* __restrict__ b2,
    const float* __restrict__ b3, float* __restrict__ out) {
    extern __shared__ char smem[];
    const uint32_t sb = s2u(smem);
    const int b = blockIdx.x, tid = threadIdx.x;
    const int warp = tid >> 5, lane = tid & 31;

    // build dinv + fp16 mask matrix (layer-invariant) straight from ballots
    float* sDinv = (float*)(smem + OFF_DINV);
    const float* ab = adj + (size_t)b * 16384;
    for (int r = warp; r < 128; r += 16) {
        const float* a = ab + r * 128;
        unsigned m[4]; int deg = 0;
#pragma unroll
        for (int s = 0; s < 4; ++s) {
            unsigned w = __ballot_sync(0xffffffffu, a[lane + 32 * s] != 0.0f);
            if (s == (r >> 5)) w |= 1u << (r & 31);
            m[s] = w; deg += __popc(w);
        }
        if (lane == 0) sDinv[r] = rsqrtf((float)deg);
        // each lane writes mask cols 4*lane .. 4*lane+3 of row r
        unsigned w = m[lane >> 3];
        int s4 = (lane & 7) * 4;
        unsigned u0 = (((w >> s4) & 1u) ? 0x3C00u : 0u) | (((w >> (s4 + 1)) & 1u) ? 0x3C000000u : 0u);
        unsigned u1 = (((w >> (s4 + 2)) & 1u) ? 0x3C00u : 0u) | (((w >> (s4 + 3)) & 1u) ? 0x3C000000u : 0u);
        *(uint2*)(smem + OFF_MSK + (r * SM + lane * 4) * 2) = make_uint2(u0, u1);
    }

    // stage x as fp16
    const float* xb = x + (size_t)b * 16384;
    for (int idx = tid; idx < 8192; idx += 512) {
        int r = idx >> 6, c2 = (idx & 63) * 2;
        *(unsigned*)(smem + OFF_HHI + (r * SH + c2) * 2) =
            pk(xb[r * 128 + c2], xb[r * 128 + c2 + 1]);
    }
    __syncthreads();

    layer<128, 256, true,  false>(smem, sb, b1, 0,     out, b);
    layer<256, 256, true,  false>(smem, sb, b2, 32768, out, b);
    layer<256, 128, false, true >(smem, sb, b3, 98304, out, b);
}

// ---------------------------------------------------------------------------
extern "C" void kernel_launch(void* const* d_in, const int* in_sizes, int n_in,
                              void* d_out, int out_size) {
    const float* x   = (const float*)d_in[0];
    const float* adj = (const float*)d_in[1];
    const float* W1  = (const float*)d_in[2];
    const float* b1  = (const float*)d_in[3];
    const float* W2  = (const float*)d_in[4];
    const float* b2  = (const float*)d_in[5];
    const float* W3  = (const float*)d_in[6];
    const float* b3  = (const float*)d_in[7];
    float* out = (float*)d_out;

    cudaFuncSetAttribute(gcn_fused, cudaFuncAttributeMaxDynamicSharedMemorySize, SMEM_SZ);
    prep_w<<<512, 256>>>(W1, W2, W3);
    gcn_fused<<<NB, 512, SMEM_SZ>>>(x, adj, b1, b2, b3, out);
}

// round 13
// speedup vs baseline: 5.8603x; 1.0259x over previous
#include <cuda_runtime.h>
#include <cuda_fp16.h>
#include <stdint.h>
#include <math.h>

#define NB 1024

__device__ __align__(16) __half g_Wh[131072];  // W1|W2|W3 row-major [FIN][FOUT], fp16

// ---- smem layout (bytes) ----
#define OFF_BIAS 0
#define OFF_DINV 1024
#define OFF_MSK  3584        // mask fp16 [128][136] (built once, layer-invariant)
#define OFF_HHI  38400       // H/T fp16 [128][264]
#define OFF_W    105984      // 2 x Whi[64][264]
#define WBUF     33792
#define SMEM_SZ  173568
#define SH 264
#define SM 136
#define SW 264

__device__ __forceinline__ uint32_t s2u(const void* p) {
    uint32_t a;
    asm("{ .reg .u64 t; cvta.to.shared.u64 t, %1; cvt.u32.u64 %0, t; }" : "=r"(a) : "l"(p));
    return a;
}
__device__ __forceinline__ unsigned pk(float a, float b) {   // lo=a, hi=b
    __half2 h = __floats2half2_rn(a, b);
    return *(unsigned*)&h;
}
__device__ __forceinline__ float elu_neg(float v) {          // v <= 0 branch
    return __expf(v) - 1.0f;
}
__device__ __forceinline__ void ldsm4(uint32_t* r, uint32_t a) {
    asm volatile("ldmatrix.sync.aligned.m8n8.x4.shared.b16 {%0,%1,%2,%3}, [%4];"
                 : "=r"(r[0]), "=r"(r[1]), "=r"(r[2]), "=r"(r[3]) : "r"(a));
}
__device__ __forceinline__ void ldsm4t(uint32_t* r, uint32_t a) {
    asm volatile("ldmatrix.sync.aligned.m8n8.x4.trans.shared.b16 {%0,%1,%2,%3}, [%4];"
                 : "=r"(r[0]), "=r"(r[1]), "=r"(r[2]), "=r"(r[3]) : "r"(a));
}
__device__ __forceinline__ void mma16816(float* c, const uint32_t* a, uint32_t b0, uint32_t b1) {
    asm volatile(
        "mma.sync.aligned.m16n8k16.row.col.f32.f16.f16.f32 "
        "{%0,%1,%2,%3}, {%4,%5,%6,%7}, {%8,%9}, {%0,%1,%2,%3};"
        : "+f"(c[0]), "+f"(c[1]), "+f"(c[2]), "+f"(c[3])
        : "r"(a[0]), "r"(a[1]), "r"(a[2]), "r"(a[3]), "r"(b0), "r"(b1));
}
__device__ __forceinline__ void cp16(uint32_t s, const void* g) {
    unsigned long long ga = (unsigned long long)__cvta_generic_to_global(g);
    asm volatile("cp.async.ca.shared.global [%0], [%1], 16;" :: "r"(s), "l"(ga) : "memory");
}
#define CP_COMMIT asm volatile("cp.async.commit_group;" ::: "memory")
#define CP_WAIT0  asm volatile("cp.async.wait_group 0;" ::: "memory")

// stage one 64-row W block into ring buffer `buf`
template <int FOUT>
__device__ __forceinline__ void stageW(uint32_t sb, int tid, int wbase, int kb, int buf) {
    const int cnt = 64 * FOUT / 8;
    for (int i = tid; i < cnt; i += 512) {
        int r = i / (FOUT / 8), c8 = (i % (FOUT / 8)) * 8;
        size_t go = (size_t)wbase + (size_t)(kb * 64 + r) * FOUT + c8;
        cp16(sb + OFF_W + buf * WBUF + (uint32_t)(r * SW + c8) * 2, g_Wh + go);
    }
}

// ---------------- prep: W fp16 row-major images ----------------
__global__ __launch_bounds__(256) void prep_w(const float* __restrict__ W1,
                                              const float* __restrict__ W2,
                                              const float* __restrict__ W3) {
    int id = blockIdx.x * 256 + threadIdx.x;   // 131072
    const float* W; int base, l;
    if (id < 32768)      { W = W1; base = 0;     l = id; }
    else if (id < 98304) { W = W2; base = 32768; l = id - 32768; }
    else                 { W = W3; base = 98304; l = id - 98304; }
    g_Wh[base + l] = __float2half_rn(W[l]);
}

// ---------------- one layer (first W block already prefetched) ----------------
template <int FIN, int FOUT, bool ELU, bool LAST, int NEXT_FOUT, int NEXT_WBASE>
__device__ __forceinline__ void layer(char* smem, uint32_t sb, const float* __restrict__ bias,
                                      int wbase, float* __restrict__ outg, int b) {
    const int tid = threadIdx.x, lane = tid & 31, wid = tid >> 5;
    const int wm = wid >> 2, wn = wid & 3;               // 4 x 4 warp grid
    constexpr int NWN = FOUT / 4, NT16 = NWN / 16, NT8 = NWN / 8, KB = FIN / 64;

    float* sBias = (float*)(smem + OFF_BIAS);
    const float* sDinv = (const float*)(smem + OFF_DINV);
    for (int n = tid; n < FOUT; n += 512) sBias[n] = bias[n];

    float acc[2][NT8][4];
#pragma unroll
    for (int m = 0; m < 2; ++m)
#pragma unroll
        for (int i = 0; i < NT8; ++i)
#pragma unroll
            for (int q = 0; q < 4; ++q) acc[m][i][q] = 0.0f;

    // first W block was prefetched by the previous layer (or kernel prologue)
    CP_WAIT0;
    __syncthreads();

    const uint32_t aRow  = (uint32_t)(wm * 32 + (lane & 15));
    const uint32_t aCol8 = (uint32_t)((lane >> 4) * 8);
    const uint32_t bRow  = (uint32_t)((lane & 7) + ((lane >> 3) & 1) * 8);
    const uint32_t bCol8 = (uint32_t)((lane >> 4) * 8);

    for (int kb = 0; kb < KB; ++kb) {
        if (kb + 1 < KB) stageW<FOUT>(sb, tid, wbase, kb + 1, (kb + 1) & 1);
        CP_COMMIT;
        uint32_t wb = sb + OFF_W + (kb & 1) * WBUF;
#pragma unroll
        for (int ks = 0; ks < 4; ++ks) {
            const int k = kb * 4 + ks;
            uint32_t ah[2][4];
#pragma unroll
            for (int m = 0; m < 2; ++m)
                ldsm4(ah[m], sb + OFF_HHI + ((aRow + 16 * m) * SH + k * 16 + aCol8) * 2);
            uint32_t bh[NT16][4];
#pragma unroll
            for (int t = 0; t < NT16; ++t)
                ldsm4t(bh[t], wb + ((ks * 16 + bRow) * SW + wn * NWN + t * 16 + bCol8) * 2);
#pragma unroll
            for (int t = 0; t < NT16; ++t)
#pragma unroll
                for (int m = 0; m < 2; ++m) {
                    mma16816(acc[m][2 * t], ah[m], bh[t][0], bh[t][1]);
                    mma16816(acc[m][2 * t + 1], ah[m], bh[t][2], bh[t][3]);
                }
        }
        CP_WAIT0;
        __syncthreads();
    }

    // prefetch NEXT layer's first W block (both ring buffers idle from here on)
    if constexpr (NEXT_FOUT > 0) {
        stageW<NEXT_FOUT>(sb, tid, NEXT_WBASE, 0, 0);
        CP_COMMIT;
    }

    // ---- epilogue1: write T * dinv_row into H buffer ----
#pragma unroll
    for (int m = 0; m < 2; ++m) {
        int r0 = wm * 32 + m * 16 + (lane >> 2), r1 = r0 + 8;
        float d0 = sDinv[r0], d1 = sDinv[r1];
#pragma unroll
        for (int i = 0; i < NT8; ++i) {
            int col = wn * NWN + i * 8 + (lane & 3) * 2;
            *(unsigned*)(smem + OFF_HHI + (r0 * SH + col) * 2) =
                pk(acc[m][i][0] * d0, acc[m][i][1] * d0);
            *(unsigned*)(smem + OFF_HHI + (r1 * SH + col) * 2) =
                pk(acc[m][i][2] * d1, acc[m][i][3] * d1);
        }
    }
    // GEMM2's B-reads for column-quarter wn depend only on epi1 writes of the
    // 4 warps with the same wn -> named barrier per wn group (ids 1..4)
    asm volatile("bar.sync %0, %1;" :: "r"(wn + 1), "r"(128) : "memory");

    // ---- GEMM2: out = Mask @ T ----
    float ac2[2][NT8][4];
#pragma unroll
    for (int m = 0; m < 2; ++m)
#pragma unroll
        for (int i = 0; i < NT8; ++i)
#pragma unroll
            for (int q = 0; q < 4; ++q) ac2[m][i][q] = 0.0f;

#pragma unroll
    for (int k = 0; k < 8; ++k) {
        uint32_t am[2][4];
#pragma unroll
        for (int m = 0; m < 2; ++m)
            ldsm4(am[m], sb + OFF_MSK + ((aRow + 16 * m) * SM + k * 16 + aCol8) * 2);
        uint32_t th[NT16][4];
#pragma unroll
        for (int t = 0; t < NT16; ++t)
            ldsm4t(th[t], sb + OFF_HHI + ((k * 16 + bRow) * SH + wn * NWN + t * 16 + bCol8) * 2);
#pragma unroll
        for (int t = 0; t < NT16; ++t)
#pragma unroll
            for (int m = 0; m < 2; ++m) {
                mma16816(ac2[m][2 * t], am[m], th[t][0], th[t][1]);
                mma16816(ac2[m][2 * t + 1], am[m], th[t][2], th[t][3]);
            }
    }
    __syncthreads();

    // ---- epilogue2: *dinv_i + bias, ELU, write next-H or global out ----
#pragma unroll
    for (int m = 0; m < 2; ++m) {
        int r0 = wm * 32 + m * 16 + (lane >> 2), r1 = r0 + 8;
        float d0 = sDinv[r0], d1 = sDinv[r1];
#pragma unroll
        for (int i = 0; i < NT8; ++i) {
            int col = wn * NWN + i * 8 + (lane & 3) * 2;
            float b0v = sBias[col], b1v = sBias[col + 1];
            float v00 = fmaf(ac2[m][i][0], d0, b0v), v01 = fmaf(ac2[m][i][1], d0, b1v);
            float v10 = fmaf(ac2[m][i][2], d1, b0v), v11 = fmaf(ac2[m][i][3], d1, b1v);
            if (ELU) {
                v00 = v00 > 0.f ? v00 : elu_neg(v00);
                v01 = v01 > 0.f ? v01 : elu_neg(v01);
                v10 = v10 > 0.f ? v10 : elu_neg(v10);
                v11 = v11 > 0.f ? v11 : elu_neg(v11);
            }
            if (LAST) {
                *(float2*)(outg + ((size_t)b * 128 + r0) * 128 + col) = make_float2(v00, v01);
                *(float2*)(outg + ((size_t)b * 128 + r1) * 128 + col) = make_float2(v10, v11);
            } else {
                *(unsigned*)(smem + OFF_HHI + (r0 * SH + col) * 2) = pk(v00, v01);
                *(unsigned*)(smem + OFF_HHI + (r1 * SH + col) * 2) = pk(v10, v11);
            }
        }
    }
    __syncthreads();
}

// ---------------- fused kernel ----------------
__global__ void __launch_bounds__(512, 1) gcn_fused(
    const float* __restrict__ x, const float* __restrict__ adj,
    const float* __restrict__ b1, const float* __restrict__ b2,
    const float* __restrict__ b3, float* __restrict__ out) {
    extern __shared__ char smem[];
    const uint32_t sb = s2u(smem);
    const int b = blockIdx.x, tid = threadIdx.x;
    const int warp = tid >> 5, lane = tid & 31;

    // prefetch layer-1's first W block under the whole prologue
    stageW<256>(sb, tid, 0, 0, 0);
    CP_COMMIT;

    // build dinv + fp16 mask matrix (layer-invariant) straight from ballots
    float* sDinv = (float*)(smem + OFF_DINV);
    const float* ab = adj + (size_t)b * 16384;
    for (int r = warp; r < 128; r += 16) {
        const float* a = ab + r * 128;
        unsigned m[4]; int deg = 0;
#pragma unroll
        for (int s = 0; s < 4; ++s) {
            unsigned w = __ballot_sync(0xffffffffu, a[lane + 32 * s] != 0.0f);
            if (s == (r >> 5)) w |= 1u << (r & 31);
            m[s] = w; deg += __popc(w);
        }
        if (lane == 0) sDinv[r] = rsqrtf((float)deg);
        unsigned w = m[lane >> 3];
        int s4 = (lane & 7) * 4;
        unsigned u0 = (((w >> s4) & 1u) ? 0x3C00u : 0u) | (((w >> (s4 + 1)) & 1u) ? 0x3C000000u : 0u);
        unsigned u1 = (((w >> (s4 + 2)) & 1u) ? 0x3C00u : 0u) | (((w >> (s4 + 3)) & 1u) ? 0x3C000000u : 0u);
        *(uint2*)(smem + OFF_MSK + (r * SM + lane * 4) * 2) = make_uint2(u0, u1);
    }

    // stage x as fp16
    const float* xb = x + (size_t)b * 16384;
    for (int idx = tid; idx < 8192; idx += 512) {
        int r = idx >> 6, c2 = (idx & 63) * 2;
        *(unsigned*)(smem + OFF_HHI + (r * SH + c2) * 2) =
            pk(xb[r * 128 + c2], xb[r * 128 + c2 + 1]);
    }
    __syncthreads();

    layer<128, 256, true,  false, 256, 32768>(smem, sb, b1, 0,     out, b);
    layer<256, 256, true,  false, 128, 98304>(smem, sb, b2, 32768, out, b);
    layer<256, 128, false, true,  0,   0    >(smem, sb, b3, 98304, out, b);
}

// ---------------------------------------------------------------------------
extern "C" void kernel_launch(void* const* d_in, const int* in_sizes, int n_in,
                              void* d_out, int out_size) {
    const float* x   = (const float*)d_in[0];
    const float* adj = (const float*)d_in[1];
    const float* W1  = (const float*)d_in[2];
    const float* b1  = (const float*)d_in[3];
    const float* W2  = (const float*)d_in[4];
    const float* b2  = (const float*)d_in[5];
    const float* W3  = (const float*)d_in[6];
    const float* b3  = (const float*)d_in[7];
    float* out = (float*)d_out;

    cudaFuncSetAttribute(gcn_fused, cudaFuncAttributeMaxDynamicSharedMemorySize, SMEM_SZ);
    prep_w<<<512, 256>>>(W1, W2, W3);
    gcn_fused<<<NB, 512, SMEM_SZ>>>(x, adj, b1, b2, b3, out);
}